// round 8
// baseline (speedup 1.0000x reference)
#include <cuda_runtime.h>
#include <math.h>
#include <stdint.h>

#define B_  4
#define T_  1024
#define H_  1024
#define NH_ 32
#define D_  32
#define M_  2
#define K_  1024
#define NC_ 32
#define BHM_ (B_*NH_*M_)

#define NLIN 3200          // q(1024) k(1024) v(1024) beta(64) mix(64)
#define WROWS 4224         // + Wout(1024)
#define WOUT_OFF 3200

// ---------------- scratch ----------------
__device__ uint32_t g_xhi [B_*T_*K_];
__device__ uint32_t g_xlo [B_*T_*K_];
__device__ uint32_t g_whi [WROWS*K_];
__device__ uint32_t g_wlo [WROWS*K_];
__device__ uint32_t g_yhi [B_*T_*H_];
__device__ uint32_t g_ylo [B_*T_*H_];
__device__ float g_lin [(size_t)B_*T_*NLIN];
__device__ float g_phiq [B_*T_*H_];   // [b,h,t,d]
__device__ float g_phik [B_*T_*H_];
__device__ float g_vt   [B_*T_*H_];
__device__ float g_beta [BHM_*T_];
__device__ float g_mix  [BHM_*T_];
__device__ float g_P    [BHM_*T_];
__device__ float g_U    [(size_t)BHM_*NC_*1024];
__device__ float g_ksum [BHM_*NC_*32];
__device__ float g_Scar [(size_t)BHM_*NC_*1024];
__device__ float g_Kcar [BHM_*NC_*32];
__device__ float g_ysum [B_*T_*H_];
__device__ float g_z    [B_*T_*H_];

// ==================== helpers ====================
__device__ __forceinline__ uint32_t smem_u32(const void* p) {
    uint32_t a;
    asm("{ .reg .u64 t; cvta.to.shared.u64 t, %1; cvt.u32.u64 %0, t; }" : "=r"(a) : "l"(p));
    return a;
}
__device__ __forceinline__ void cp_async16(uint32_t dst, const void* src) {
    asm volatile("cp.async.ca.shared.global [%0], [%1], 16;" :: "r"(dst), "l"(src));
}
__device__ __forceinline__ void cp_commit() { asm volatile("cp.async.commit_group;"); }
template<int N> __device__ __forceinline__ void cp_wait() {
    asm volatile("cp.async.wait_group %0;" :: "n"(N));
}
__device__ __forceinline__ uint32_t f2tf32(float x) {
    uint32_t u;
    asm("cvt.rna.tf32.f32 %0, %1;" : "=r"(u) : "f"(x));
    return u;
}
__device__ __forceinline__ void mma_tf32x(float* c, const uint32_t* a, const uint32_t* b) {
    asm volatile("mma.sync.aligned.m16n8k8.row.col.f32.tf32.tf32.f32 "
        "{%0,%1,%2,%3}, {%4,%5,%6,%7}, {%8,%9}, {%0,%1,%2,%3};"
        : "+f"(c[0]), "+f"(c[1]), "+f"(c[2]), "+f"(c[3])
        : "r"(a[0]), "r"(a[1]), "r"(a[2]), "r"(a[3]), "r"(b[0]), "r"(b[1]));
}

// ---------------- tf32 hi/lo split ----------------
__global__ __launch_bounds__(256) void split_kernel(
    const float* __restrict__ src, uint32_t* __restrict__ hi,
    uint32_t* __restrict__ lo, int n4)
{
    int i = blockIdx.x * 256 + threadIdx.x;
    if (i >= n4) return;
    float4 v = ((const float4*)src)[i];
    uint4 h, l;
    h.x = f2tf32(v.x); l.x = f2tf32(v.x - __uint_as_float(h.x));
    h.y = f2tf32(v.y); l.y = f2tf32(v.y - __uint_as_float(h.y));
    h.z = f2tf32(v.z); l.z = f2tf32(v.z - __uint_as_float(h.z));
    h.w = f2tf32(v.w); l.w = f2tf32(v.w - __uint_as_float(h.w));
    ((uint4*)hi)[i] = h;
    ((uint4*)lo)[i] = l;
}

// ==================== pre-split tf32x3 GEMM ====================
// C[M,N] = A[M,K].B[N,K]^T, operands pre-split into tf32 hi/lo.
// CTA 128x128, KC=8, 4-stage cp.async pipeline, 2 CTAs/SM.
// MODE 0: fused qkv+beta+mix -> g_lin (ldc=NLIN). MODE 2: out proj + bias + residual (ldc=H_).

#define NSTG 4
#define ST_WORDS 6144              // 4 arrays x 128 rows x 12 words
#define GSMEM_BYTES (NSTG*ST_WORDS*4)   // 98304

template<int MODE>
__global__ void __launch_bounds__(256, 2) gemm_sp(
    const uint32_t* __restrict__ Ahi, const uint32_t* __restrict__ Alo,
    const uint32_t* __restrict__ Bhi, const uint32_t* __restrict__ Blo,
    float* __restrict__ C, const float* __restrict__ bias, const float* __restrict__ xres)
{
    extern __shared__ uint32_t sm[];
    const uint32_t sa = smem_u32(sm);
    const int tid  = threadIdx.x;
    const int row0 = blockIdx.y * 128;
    const int col0 = blockIdx.x * 128;
    const int lane = tid & 31;
    const int wm = ((tid >> 7) & 1) * 64;
    const int wn = ((tid >> 5) & 3) * 32;

    const int ldrow = tid >> 1;
    const int half  = tid & 1;
    const uint32_t off = (uint32_t)((ldrow * 12 + half * 4) * 4);

    const uint32_t* ahp = Ahi + (size_t)(row0 + ldrow) * K_ + half * 4;
    const uint32_t* alp = Alo + (size_t)(row0 + ldrow) * K_ + half * 4;
    const uint32_t* bhp = Bhi + (size_t)(col0 + ldrow) * K_ + half * 4;
    const uint32_t* blp = Blo + (size_t)(col0 + ldrow) * K_ + half * 4;

#define ISSUE(ch, stg) do { \
    uint32_t _b = sa + (uint32_t)(stg) * (ST_WORDS * 4); \
    cp_async16(_b + off,         ahp + (ch) * 8); \
    cp_async16(_b + 6144  + off, alp + (ch) * 8); \
    cp_async16(_b + 12288 + off, bhp + (ch) * 8); \
    cp_async16(_b + 18432 + off, blp + (ch) * 8); \
    cp_commit(); } while (0)

    ISSUE(0, 0); ISSUE(1, 1); ISSUE(2, 2);

    float cc[64];
#pragma unroll
    for (int x = 0; x < 64; x++) cc[x] = 0.f;

#define MMALOOP(AA, BB) do { \
    _Pragma("unroll") \
    for (int mt = 0; mt < 4; mt++) \
    _Pragma("unroll") \
    for (int nt = 0; nt < 4; nt++) \
        mma_tf32x(&cc[(mt*4+nt)*4], &(AA)[mt*4], &(BB)[nt*2]); } while (0)

    int ab[4], bb2[4];
#pragma unroll
    for (int mt = 0; mt < 4; mt++)
        ab[mt] = (wm + mt * 16 + (lane >> 2)) * 12 + (lane & 3);
#pragma unroll
    for (int nt = 0; nt < 4; nt++)
        bb2[nt] = (wn + nt * 8 + (lane >> 2)) * 12 + (lane & 3);

#pragma unroll 4
    for (int i = 0; i < 128; i++) {
        if (i < 126)       cp_wait<2>();
        else if (i == 126) cp_wait<1>();
        else               cp_wait<0>();
        __syncthreads();
        if (i + 3 < 128) ISSUE(i + 3, (i + 3) & 3);

        const uint32_t* Ah = sm + (i & 3) * ST_WORDS;
        const uint32_t* Al = Ah + 1536;
        const uint32_t* Bh = Ah + 3072;
        const uint32_t* Bl = Ah + 4608;

        uint32_t ah[16], bh[8];
#pragma unroll
        for (int mt = 0; mt < 4; mt++) {
            ah[mt*4+0] = Ah[ab[mt]];
            ah[mt*4+1] = Ah[ab[mt] + 96];
            ah[mt*4+2] = Ah[ab[mt] + 4];
            ah[mt*4+3] = Ah[ab[mt] + 100];
        }
#pragma unroll
        for (int nt = 0; nt < 4; nt++) {
            bh[nt*2+0] = Bh[bb2[nt]];
            bh[nt*2+1] = Bh[bb2[nt] + 4];
        }
        MMALOOP(ah, bh);
        {
            uint32_t al[16];
#pragma unroll
            for (int mt = 0; mt < 4; mt++) {
                al[mt*4+0] = Al[ab[mt]];
                al[mt*4+1] = Al[ab[mt] + 96];
                al[mt*4+2] = Al[ab[mt] + 4];
                al[mt*4+3] = Al[ab[mt] + 100];
            }
            MMALOOP(al, bh);
        }
        {
            uint32_t bl[8];
#pragma unroll
            for (int nt = 0; nt < 4; nt++) {
                bl[nt*2+0] = Bl[bb2[nt]];
                bl[nt*2+1] = Bl[bb2[nt] + 4];
            }
            MMALOOP(ah, bl);
        }
    }

    // ---- epilogue ----
    const int ldc = (MODE == 0) ? NLIN : H_;
#pragma unroll
    for (int mt = 0; mt < 4; mt++)
#pragma unroll
    for (int nt = 0; nt < 4; nt++) {
        const int r = row0 + wm + mt * 16 + (lane >> 2);
        const int c = col0 + wn + nt * 8 + (lane & 3) * 2;
        float* p = &cc[(mt*4+nt)*4];
        if (MODE == 0) {
            *(float2*)&C[(size_t)r * ldc + c]     = make_float2(p[0], p[1]);
            *(float2*)&C[(size_t)(r+8) * ldc + c] = make_float2(p[2], p[3]);
        } else {
            const size_t o0 = (size_t)r * ldc + c, o1 = (size_t)(r+8) * ldc + c;
            float2 x0 = *(const float2*)&xres[o0];
            float2 x1 = *(const float2*)&xres[o1];
            float2 bv = *(const float2*)&bias[c];
            *(float2*)&C[o0] = make_float2(p[0] + bv.x + x0.x, p[1] + bv.y + x0.y);
            *(float2*)&C[o1] = make_float2(p[2] + bv.x + x1.x, p[3] + bv.y + x1.y);
        }
    }
#undef ISSUE
#undef MMALOOP
}

// ---------------- prep: RoPE + phi, beta, mix, v transpose (reads g_lin) ----------------
__global__ __launch_bounds__(512) void prep_kernel(
    const float* __restrict__ lin, const float* __restrict__ bbeta,
    const float* __restrict__ bmix,
    float* __restrict__ phiq, float* __restrict__ phik, float* __restrict__ vt,
    float* __restrict__ beta, float* __restrict__ mixo)
{
    const int bt = blockIdx.x;
    const int b  = bt >> 10;
    const int t  = bt & 1023;
    const int tid = threadIdx.x;
    const int h  = tid >> 4;
    const int i  = tid & 15;

    float inv = expf(-(float)i * (0.0625f * 9.210340371976184f));
    float ang = (float)t * inv;
    float s = sinf(ang), c = cosf(ang);

    const size_t rb = (size_t)bt * NLIN;
    size_t src = rb + (size_t)h * 32;
    float q1 = lin[src + i],        q2 = lin[src + 16 + i];
    float k1 = lin[src + 1024 + i], k2 = lin[src + 1024 + 16 + i];
    float rq1 = q1*c - q2*s, rq2 = q1*s + q2*c;
    float rk1 = k1*c - k2*s, rk2 = k1*s + k2*c;

    size_t dst = (((size_t)b * NH_ + h) * T_ + t) * D_;
    phiq[dst + i]      = (rq1 > 0.f) ? rq1 + 1.f : expf(rq1);
    phiq[dst + 16 + i] = (rq2 > 0.f) ? rq2 + 1.f : expf(rq2);
    phik[dst + i]      = (rk1 > 0.f) ? rk1 + 1.f : expf(rk1);
    phik[dst + 16 + i] = (rk2 > 0.f) ? rk2 + 1.f : expf(rk2);

    {
        int e  = tid * 2;
        int hh = e >> 5, dd = e & 31;
        float2 vv = *(const float2*)(lin + rb + 2048 + e);
        size_t vd = (((size_t)b * NH_ + hh) * T_ + t) * D_ + dd;
        *(float2*)(vt + vd) = vv;
    }

    if (tid < 64) {
        float xv = lin[rb + 3072 + tid] + bbeta[tid];
        float sg = 1.f / (1.f + expf(-xv));
        sg = fminf(fmaxf(sg, 0.85f), 0.9995f);
        int hh = tid >> 1, mm = tid & 1;
        beta[(((size_t)b * NH_ + hh) * M_ + mm) * T_ + t] = sg;
    }
    if (tid < 32) {
        int hh = tid;
        float a0 = lin[rb + 3136 + hh*2]     + bmix[hh*2];
        float a1 = lin[rb + 3136 + hh*2 + 1] + bmix[hh*2 + 1];
        float mx = fmaxf(a0, a1);
        float e0 = expf(a0 - mx), e1 = expf(a1 - mx);
        float rinv = 1.f / (e0 + e1);
        size_t base = (((size_t)b * NH_ + hh) * M_) * T_ + t;
        mixo[base]      = e0 * rinv;
        mixo[base + T_] = e1 * rinv;
    }
}

// ---------------- chunk-local cumprod of beta ----------------
__global__ __launch_bounds__(32) void cumprod_kernel(
    const float* __restrict__ beta, float* __restrict__ P)
{
    const int blk = blockIdx.x;
    const int bhm = blk >> 5, c = blk & 31;
    const int lane = threadIdx.x;
    size_t idx = (size_t)bhm * T_ + c * 32 + lane;
    float v = beta[idx];
#pragma unroll
    for (int o = 1; o < 32; o <<= 1) {
        float u = __shfl_up_sync(0xffffffffu, v, o);
        if (lane >= o) v *= u;
    }
    P[idx] = v;
}

// ---------------- per-chunk U = K~^T V (stored [e][d]) and ksum ----------------
__global__ __launch_bounds__(256) void chunk_sum_kernel(
    const float* __restrict__ phik, const float* __restrict__ vt,
    const float* __restrict__ P, float* __restrict__ U, float* __restrict__ ksum)
{
    const int blk = blockIdx.x;
    const int bhm = blk >> 5, c = blk & 31;
    const int bh  = bhm >> 1;
    const int t0  = c * 32;

    __shared__ float kt[32][33];
    __shared__ float vv[32][33];

    const int tl = threadIdx.x >> 3;
    const int x4 = (threadIdx.x & 7) * 4;

    float Pt  = P[(size_t)bhm * T_ + t0 + tl];
    float inv = 1.f / Pt;
    size_t base = ((size_t)bh * T_ + t0 + tl) * 32 + x4;
    float4 kv = *(const float4*)(phik + base);
    kt[tl][x4+0] = kv.x * inv; kt[tl][x4+1] = kv.y * inv;
    kt[tl][x4+2] = kv.z * inv; kt[tl][x4+3] = kv.w * inv;
    float4 vz = *(const float4*)(vt + base);
    vv[tl][x4+0] = vz.x; vv[tl][x4+1] = vz.y; vv[tl][x4+2] = vz.z; vv[tl][x4+3] = vz.w;
    __syncthreads();

    const int e = tl;
    float a0 = 0.f, a1 = 0.f, a2 = 0.f, a3 = 0.f;
#pragma unroll
    for (int t = 0; t < 32; t++) {
        float ve = vv[t][e];
        a0 = fmaf(kt[t][x4+0], ve, a0);
        a1 = fmaf(kt[t][x4+1], ve, a1);
        a2 = fmaf(kt[t][x4+2], ve, a2);
        a3 = fmaf(kt[t][x4+3], ve, a3);
    }
    *(float4*)(U + (size_t)blk * 1024 + e * 32 + x4) = make_float4(a0, a1, a2, a3);

    if (threadIdx.x < 32) {
        int d = threadIdx.x;
        float s = 0.f;
#pragma unroll
        for (int t = 0; t < 32; t++) s += kt[t][d];
        ksum[(size_t)blk * 32 + d] = s;
    }
}

// ---------------- sequential carry over chunks ----------------
__global__ __launch_bounds__(32) void carry_kernel(
    const float* __restrict__ P, const float* __restrict__ U,
    const float* __restrict__ ksum, float* __restrict__ Scar, float* __restrict__ Kcar)
{
    const int bhm = blockIdx.x;
    const int e = threadIdx.x;
    float S[32];
#pragma unroll
    for (int d = 0; d < 32; d++) S[d] = 0.f;
    float Kv = 0.f;

    for (int c = 0; c < NC_; c++) {
        size_t tb = (size_t)bhm * NC_ + c;
        float* sd = Scar + tb * 1024 + e * 32;
#pragma unroll
        for (int q = 0; q < 8; q++)
            ((float4*)sd)[q] = make_float4(S[4*q], S[4*q+1], S[4*q+2], S[4*q+3]);
        Kcar[tb * 32 + e] = Kv;

        float PL = P[(size_t)bhm * T_ + c * 32 + 31];
        const float* ud = U + tb * 1024 + e * 32;
#pragma unroll
        for (int q = 0; q < 8; q++) {
            float4 u = ((const float4*)ud)[q];
            S[4*q+0] = PL * (S[4*q+0] + u.x);
            S[4*q+1] = PL * (S[4*q+1] + u.y);
            S[4*q+2] = PL * (S[4*q+2] + u.z);
            S[4*q+3] = PL * (S[4*q+3] + u.w);
        }
        Kv = PL * (Kv + ksum[tb * 32 + e]);
    }
}

// ---------------- per-chunk output ----------------
__global__ __launch_bounds__(256) void chunk_out_kernel(
    const float* __restrict__ phiq, const float* __restrict__ phik,
    const float* __restrict__ vt,   const float* __restrict__ P,
    const float* __restrict__ mix,  const float* __restrict__ Scar,
    const float* __restrict__ Kcar, float* __restrict__ y)
{
    const int blk = blockIdx.x;
    const int bh = blk >> 5, c = blk & 31;
    const int t0 = c * 32;

    __shared__ float qt[32][33];
    __shared__ float kt[32][33];
    __shared__ float vv[32][33];
    __shared__ float ST[32][33];
    __shared__ float A [32][33];
    __shared__ float den[32];
    __shared__ float K0[32];

    const int tid = threadIdx.x;
    const int tl = tid >> 3;
    const int x4 = (tid & 7) * 4;
    const int lane = tid & 31, w = tid >> 5;

    size_t vbase = ((size_t)bh * T_ + t0 + tl) * 32 + x4;
    {
        float4 vz = *(const float4*)(vt + vbase);
        vv[tl][x4+0] = vz.x; vv[tl][x4+1] = vz.y; vv[tl][x4+2] = vz.z; vv[tl][x4+3] = vz.w;
    }

    float yac[4] = {0.f, 0.f, 0.f, 0.f};

    for (int m = 0; m < 2; m++) {
        const int bhm = bh * 2 + m;
        float Pt  = P[(size_t)bhm * T_ + t0 + tl];
        float inv = 1.f / Pt;
        float4 qv = *(const float4*)(phiq + vbase);
        float4 kv = *(const float4*)(phik + vbase);
        qt[tl][x4+0] = qv.x * Pt;  qt[tl][x4+1] = qv.y * Pt;
        qt[tl][x4+2] = qv.z * Pt;  qt[tl][x4+3] = qv.w * Pt;
        kt[tl][x4+0] = kv.x * inv; kt[tl][x4+1] = kv.y * inv;
        kt[tl][x4+2] = kv.z * inv; kt[tl][x4+3] = kv.w * inv;

        size_t tb = (size_t)bhm * NC_ + c;
        float4 sv = ((const float4*)(Scar + tb * 1024))[tid];
        ST[tl][x4+0] = sv.x; ST[tl][x4+1] = sv.y; ST[tl][x4+2] = sv.z; ST[tl][x4+3] = sv.w;
        if (tid < 32) K0[tid] = Kcar[tb * 32 + tid];
        __syncthreads();

        float a[4] = {0.f, 0.f, 0.f, 0.f};
#pragma unroll
        for (int d = 0; d < 32; d++) {
            float qd = qt[tl][d];
            a[0] = fmaf(qd, kt[x4+0][d], a[0]);
            a[1] = fmaf(qd, kt[x4+1][d], a[1]);
            a[2] = fmaf(qd, kt[x4+2][d], a[2]);
            a[3] = fmaf(qd, kt[x4+3][d], a[3]);
        }
#pragma unroll
        for (int q = 0; q < 4; q++)
            A[tl][x4+q] = (x4 + q <= tl) ? a[q] : 0.f;
        __syncthreads();

#pragma unroll
        for (int r = 0; r < 4; r++) {
            int t = w * 4 + r;
            float v = A[t][lane] + qt[t][lane] * K0[lane];
#pragma unroll
            for (int o = 16; o > 0; o >>= 1)
                v += __shfl_xor_sync(0xffffffffu, v, o);
            if (lane == 0) den[t] = v + 1e-6f;
        }
        __syncthreads();

        float mixv = mix[(size_t)bhm * T_ + t0 + tl];
        float f = mixv / den[tl];
        float n[4] = {0.f, 0.f, 0.f, 0.f};
#pragma unroll
        for (int j = 0; j < 32; j++) {
            float aj = A[tl][j];
            n[0] = fmaf(aj, vv[j][x4+0], n[0]);
            n[1] = fmaf(aj, vv[j][x4+1], n[1]);
            n[2] = fmaf(aj, vv[j][x4+2], n[2]);
            n[3] = fmaf(aj, vv[j][x4+3], n[3]);
        }
#pragma unroll
        for (int d = 0; d < 32; d++) {
            float qd = qt[tl][d];
            n[0] = fmaf(qd, ST[x4+0][d], n[0]);
            n[1] = fmaf(qd, ST[x4+1][d], n[1]);
            n[2] = fmaf(qd, ST[x4+2][d], n[2]);
            n[3] = fmaf(qd, ST[x4+3][d], n[3]);
        }
#pragma unroll
        for (int q = 0; q < 4; q++) yac[q] = fmaf(f, n[q], yac[q]);
        __syncthreads();
    }

    const int b = bh >> 5, h = bh & 31;
    *(float4*)(y + ((size_t)(b * T_ + t0 + tl)) * H_ + h * 32 + x4)
        = make_float4(yac[0], yac[1], yac[2], yac[3]);
}

// ---------------- LayerNorm ----------------
__global__ __launch_bounds__(256) void ln_kernel(
    const float* __restrict__ z, const float* __restrict__ gamma,
    const float* __restrict__ bta, float* __restrict__ out)
{
    const int row = blockIdx.x;
    const float* zr = z + (size_t)row * H_;
    float s = 0.f, ss = 0.f;
    for (int i = threadIdx.x; i < H_; i += 256) {
        float v = zr[i]; s += v; ss = fmaf(v, v, ss);
    }
    __shared__ float sh[64];
#pragma unroll
    for (int o = 16; o > 0; o >>= 1) {
        s  += __shfl_xor_sync(0xffffffffu, s, o);
        ss += __shfl_xor_sync(0xffffffffu, ss, o);
    }
    int wid = threadIdx.x >> 5, lane = threadIdx.x & 31;
    if (lane == 0) { sh[wid] = s; sh[32 + wid] = ss; }
    __syncthreads();
    if (threadIdx.x < 32) {
        float a = (threadIdx.x < 8) ? sh[threadIdx.x] : 0.f;
        float c = (threadIdx.x < 8) ? sh[32 + threadIdx.x] : 0.f;
#pragma unroll
        for (int o = 4; o > 0; o >>= 1) {
            a += __shfl_xor_sync(0xffffffffu, a, o);
            c += __shfl_xor_sync(0xffffffffu, c, o);
        }
        if (threadIdx.x == 0) { sh[0] = a; sh[1] = c; }
    }
    __syncthreads();
    float mu  = sh[0] * (1.f / H_);
    float var = sh[1] * (1.f / H_) - mu * mu;
    float rstd = rsqrtf(var + 1e-5f);
    for (int i = threadIdx.x; i < H_; i += 256)
        out[(size_t)row * H_ + i] = (zr[i] - mu) * rstd * gamma[i] + bta[i];
}

// ---------------- launch ----------------
extern "C" void kernel_launch(void* const* d_in, const int* in_sizes, int n_in,
                              void* d_out, int out_size)
{
    const float* x     = (const float*)d_in[0];
    const float* Wq    = (const float*)d_in[1];
    const float* Wk    = (const float*)d_in[2];
    const float* Wv    = (const float*)d_in[3];
    const float* Wbeta = (const float*)d_in[4];
    const float* bbeta = (const float*)d_in[5];
    const float* Wmix  = (const float*)d_in[6];
    const float* bmix  = (const float*)d_in[7];
    const float* Wout  = (const float*)d_in[8];
    const float* bout  = (const float*)d_in[9];
    const float* ln_g  = (const float*)d_in[10];
    const float* ln_b  = (const float*)d_in[11];
    float* out = (float*)d_out;

    uint32_t *xhi,*xlo,*whi,*wlo,*yhi,*ylo;
    float *lin,*phiq,*phik,*vt,*beta,*mix,*P,*U,*ksum,*Scar,*Kcar,*ysum,*z;
    cudaGetSymbolAddress((void**)&xhi, g_xhi);
    cudaGetSymbolAddress((void**)&xlo, g_xlo);
    cudaGetSymbolAddress((void**)&whi, g_whi);
    cudaGetSymbolAddress((void**)&wlo, g_wlo);
    cudaGetSymbolAddress((void**)&yhi, g_yhi);
    cudaGetSymbolAddress((void**)&ylo, g_ylo);
    cudaGetSymbolAddress((void**)&lin, g_lin);
    cudaGetSymbolAddress((void**)&phiq, g_phiq);
    cudaGetSymbolAddress((void**)&phik, g_phik);
    cudaGetSymbolAddress((void**)&vt,   g_vt);
    cudaGetSymbolAddress((void**)&beta, g_beta);
    cudaGetSymbolAddress((void**)&mix,  g_mix);
    cudaGetSymbolAddress((void**)&P,    g_P);
    cudaGetSymbolAddress((void**)&U,    g_U);
    cudaGetSymbolAddress((void**)&ksum, g_ksum);
    cudaGetSymbolAddress((void**)&Scar, g_Scar);
    cudaGetSymbolAddress((void**)&Kcar, g_Kcar);
    cudaGetSymbolAddress((void**)&ysum, g_ysum);
    cudaGetSymbolAddress((void**)&z,    g_z);

    cudaFuncSetAttribute(gemm_sp<0>, cudaFuncAttributeMaxDynamicSharedMemorySize, GSMEM_BYTES);
    cudaFuncSetAttribute(gemm_sp<2>, cudaFuncAttributeMaxDynamicSharedMemorySize, GSMEM_BYTES);

    // ---- pre-split operands into tf32 hi/lo ----
    split_kernel<<<4096, 256>>>(x,     xhi, xlo, (B_*T_*K_)/4);
    split_kernel<<<1024, 256>>>(Wq,    whi + 0*1024*1024/1, wlo + 0,        (1024*K_)/4);
    split_kernel<<<1024, 256>>>(Wk,    whi + 1024*K_,       wlo + 1024*K_,  (1024*K_)/4);
    split_kernel<<<1024, 256>>>(Wv,    whi + 2048*K_,       wlo + 2048*K_,  (1024*K_)/4);
    split_kernel<<<64,   256>>>(Wbeta, whi + 3072*K_,       wlo + 3072*K_,  (64*K_)/4);
    split_kernel<<<64,   256>>>(Wmix,  whi + 3136*K_,       wlo + 3136*K_,  (64*K_)/4);
    split_kernel<<<1024, 256>>>(Wout,  whi + (size_t)WOUT_OFF*K_, wlo + (size_t)WOUT_OFF*K_, (1024*K_)/4);

    // ---- fused q/k/v/beta/mix projection ----
    gemm_sp<0><<<dim3(NLIN/128, 32), 256, GSMEM_BYTES>>>(
        xhi, xlo, whi, wlo, lin, nullptr, nullptr);

    prep_kernel<<<B_*T_, 512>>>(lin, bbeta, bmix, phiq, phik, vt, beta, mix);

    cumprod_kernel<<<BHM_*NC_, 32>>>(beta, P);
    chunk_sum_kernel<<<BHM_*NC_, 256>>>(phik, vt, P, U, ksum);
    carry_kernel<<<BHM_, 32>>>(P, U, ksum, Scar, Kcar);
    chunk_out_kernel<<<B_*NH_*NC_, 256>>>(phiq, phik, vt, P, mix, Scar, Kcar, ysum);

    // ---- output projection ----
    split_kernel<<<4096, 256>>>(ysum, yhi, ylo, (B_*T_*H_)/4);
    gemm_sp<2><<<dim3(8, 32), 256, GSMEM_BYTES>>>(
        yhi, ylo, whi + (size_t)WOUT_OFF*K_, wlo + (size_t)WOUT_OFF*K_, z, bout, x);

    ln_kernel<<<B_*T_, 256>>>(z, ln_g, ln_b, out);
}

// round 9
// speedup vs baseline: 1.3096x; 1.3096x over previous
#include <cuda_runtime.h>
#include <math.h>
#include <stdint.h>

#define B_  4
#define T_  1024
#define H_  1024
#define NH_ 32
#define D_  32
#define M_  2
#define K_  1024
#define NC_ 32
#define BHM_ (B_*NH_*M_)
#define NLIN 3200          // q(1024) k(1024) v(1024) beta(64) mix(64)

// ---------------- scratch ----------------
__device__ float g_lin [(size_t)B_*T_*NLIN];
__device__ float g_phiq [B_*T_*H_];   // [b,h,t,d]
__device__ float g_phik [B_*T_*H_];
__device__ float g_vt   [B_*T_*H_];
__device__ float g_beta [BHM_*T_];
__device__ float g_mix  [BHM_*T_];
__device__ float g_P    [BHM_*T_];
__device__ float g_U    [(size_t)BHM_*NC_*1024];
__device__ float g_ksum [BHM_*NC_*32];
__device__ float g_Scar [(size_t)BHM_*NC_*1024];
__device__ float g_Kcar [BHM_*NC_*32];
__device__ float g_ysum [B_*T_*H_];
__device__ float g_z    [B_*T_*H_];

// ==================== helpers ====================
__device__ __forceinline__ uint32_t smem_u32(const void* p) {
    uint32_t a;
    asm("{ .reg .u64 t; cvta.to.shared.u64 t, %1; cvt.u32.u64 %0, t; }" : "=r"(a) : "l"(p));
    return a;
}
__device__ __forceinline__ void cp_async16(uint32_t dst, const void* src) {
    asm volatile("cp.async.ca.shared.global [%0], [%1], 16;" :: "r"(dst), "l"(src));
}
__device__ __forceinline__ void cp_commit() { asm volatile("cp.async.commit_group;"); }
template<int N> __device__ __forceinline__ void cp_wait() {
    asm volatile("cp.async.wait_group %0;" :: "n"(N));
}
__device__ __forceinline__ uint32_t f2tf32(float x) {
    uint32_t u;
    asm("cvt.rna.tf32.f32 %0, %1;" : "=r"(u) : "f"(x));
    return u;
}
__device__ __forceinline__ void mma_tf32x(float* c, const uint32_t* a, const uint32_t* b) {
    asm volatile("mma.sync.aligned.m16n8k8.row.col.f32.tf32.tf32.f32 "
        "{%0,%1,%2,%3}, {%4,%5,%6,%7}, {%8,%9}, {%0,%1,%2,%3};"
        : "+f"(c[0]), "+f"(c[1]), "+f"(c[2]), "+f"(c[3])
        : "r"(a[0]), "r"(a[1]), "r"(a[2]), "r"(a[3]), "r"(b[0]), "r"(b[1]));
}

// ==================== tf32x3 mma.sync GEMM (R7 internals) ====================
// CTA 128x128, KC=16, 3-stage cp.async pipeline, 2 CTAs/SM, on-the-fly tf32 split.
// MODE 0: fused q/k/v/beta/mix -> lin[4096][3200], B selected by blockIdx.x.
// MODE 2: out projection + bias + residual (ldc = H_).

#define KC 16
#define NCH 64
#define S_WORDS 12
#define SLICE_FL (128*S_WORDS)
#define STG_FL (2*SLICE_FL)
#define A_FL (3*STG_FL)
#define GSMEM_BYTES (2*A_FL*4)       // 73728 B

template<int MODE>
__global__ void __launch_bounds__(256, 2) gemm_mma(
    const float* __restrict__ A,
    const float* __restrict__ W0, const float* __restrict__ W1,
    const float* __restrict__ W2, const float* __restrict__ W3,
    const float* __restrict__ W4,
    float* __restrict__ C,
    const float* __restrict__ bias, const float* __restrict__ xres)
{
    extern __shared__ float sm[];
    float* As = sm;
    float* Bs = sm + A_FL;

    const int tid  = threadIdx.x;
    const int row0 = blockIdx.y * 128;
    const int col0 = blockIdx.x * 128;
    const int lane = tid & 31;
    const int wm = ((tid >> 7) & 1) * 64;
    const int wn = ((tid >> 5) & 3) * 32;

    const int ldrow = tid >> 1;
    const int half  = tid & 1;
    const float* asrc = A + (size_t)(row0 + ldrow) * K_ + half * 8;
    const float* bsrc;
    if (MODE == 0) {
        const int bx = blockIdx.x;
        if (bx < 8)       bsrc = W0 + (size_t)(col0 + ldrow) * K_;
        else if (bx < 16) bsrc = W1 + (size_t)(col0 - 1024 + ldrow) * K_;
        else if (bx < 24) bsrc = W2 + (size_t)(col0 - 2048 + ldrow) * K_;
        else bsrc = (ldrow < 64) ? W3 + (size_t)ldrow * K_
                                 : W4 + (size_t)(ldrow - 64) * K_;
        bsrc += half * 8;
    } else {
        bsrc = W0 + (size_t)(col0 + ldrow) * K_ + half * 8;
    }

    const uint32_t sa = smem_u32(sm);
    uint32_t offs[2];
#pragma unroll
    for (int q = 0; q < 2; q++)
        offs[q] = (uint32_t)((((half * 128 + ldrow) * S_WORDS) + q * 4) * 4);

#define ISSUE(chunk, stg) do { \
    const float* _ap = asrc + (chunk) * KC; \
    const float* _bp = bsrc + (chunk) * KC; \
    uint32_t _b = sa + (uint32_t)(stg) * (STG_FL * 4); \
    cp_async16(_b + offs[0], _ap); \
    cp_async16(_b + offs[1], _ap + 4); \
    cp_async16(_b + (uint32_t)(A_FL * 4) + offs[0], _bp); \
    cp_async16(_b + (uint32_t)(A_FL * 4) + offs[1], _bp + 4); \
    cp_commit(); } while (0)

    ISSUE(0, 0); ISSUE(1, 1); ISSUE(2, 2);

    float cc[64];
#pragma unroll
    for (int x = 0; x < 64; x++) cc[x] = 0.f;

#define MMALOOP(AA, BB) do { \
    _Pragma("unroll") \
    for (int mt = 0; mt < 4; mt++) \
    _Pragma("unroll") \
    for (int nt = 0; nt < 4; nt++) \
        mma_tf32x(&cc[(mt*4+nt)*4], &(AA)[mt*4], &(BB)[nt*2]); } while (0)

    int stg = 0;
    for (int i = 0; i < NCH; i++) {
        if (i <= NCH - 3)      cp_wait<2>();
        else if (i == NCH - 2) cp_wait<1>();
        else                   cp_wait<0>();
        __syncthreads();
        const float* Ab = As + stg * STG_FL;
        const float* Bb = Bs + stg * STG_FL;

#pragma unroll
        for (int s = 0; s < 2; s++) {
            const float* Asl = Ab + s * SLICE_FL;
            const float* Bsl = Bb + s * SLICE_FL;
            float af[16], bf[8];
#pragma unroll
            for (int mt = 0; mt < 4; mt++) {
                int base = (wm + mt * 16 + (lane >> 2)) * S_WORDS + (lane & 3);
                af[mt*4+0] = Asl[base];
                af[mt*4+1] = Asl[base + 8 * S_WORDS];
                af[mt*4+2] = Asl[base + 4];
                af[mt*4+3] = Asl[base + 8 * S_WORDS + 4];
            }
#pragma unroll
            for (int nt = 0; nt < 4; nt++) {
                int base = (wn + nt * 8 + (lane >> 2)) * S_WORDS + (lane & 3);
                bf[nt*2+0] = Bsl[base];
                bf[nt*2+1] = Bsl[base + 4];
            }
            uint32_t ah[16], bh[8];
#pragma unroll
            for (int x = 0; x < 16; x++) ah[x] = f2tf32(af[x]);
#pragma unroll
            for (int x = 0; x < 8;  x++) bh[x] = f2tf32(bf[x]);
            MMALOOP(ah, bh);
            {
                uint32_t al[16];
#pragma unroll
                for (int x = 0; x < 16; x++) al[x] = f2tf32(af[x] - __uint_as_float(ah[x]));
                MMALOOP(al, bh);
            }
            {
                uint32_t bl[8];
#pragma unroll
                for (int x = 0; x < 8; x++) bl[x] = f2tf32(bf[x] - __uint_as_float(bh[x]));
                MMALOOP(ah, bl);
            }
        }
        __syncthreads();
        if (i + 3 < NCH) ISSUE(i + 3, stg);
        stg = (stg == 2) ? 0 : stg + 1;
    }

    // ---- epilogue ----
    const int ldc = (MODE == 0) ? NLIN : H_;
#pragma unroll
    for (int mt = 0; mt < 4; mt++)
#pragma unroll
    for (int nt = 0; nt < 4; nt++) {
        const int r = row0 + wm + mt * 16 + (lane >> 2);
        const int c = col0 + wn + nt * 8 + (lane & 3) * 2;
        float* p = &cc[(mt*4+nt)*4];
        if (MODE == 0) {
            *(float2*)&C[(size_t)r * ldc + c]     = make_float2(p[0], p[1]);
            *(float2*)&C[(size_t)(r+8) * ldc + c] = make_float2(p[2], p[3]);
        } else {
            const size_t o0 = (size_t)r * ldc + c, o1 = (size_t)(r+8) * ldc + c;
            float2 x0 = *(const float2*)&xres[o0];
            float2 x1 = *(const float2*)&xres[o1];
            float2 bv = *(const float2*)&bias[c];
            *(float2*)&C[o0] = make_float2(p[0] + bv.x + x0.x, p[1] + bv.y + x0.y);
            *(float2*)&C[o1] = make_float2(p[2] + bv.x + x1.x, p[3] + bv.y + x1.y);
        }
    }
#undef ISSUE
#undef MMALOOP
}

// ---------------- prep: RoPE + phi, beta, mix, v transpose (reads g_lin) ----------------
__global__ __launch_bounds__(512) void prep_kernel(
    const float* __restrict__ lin, const float* __restrict__ bbeta,
    const float* __restrict__ bmix,
    float* __restrict__ phiq, float* __restrict__ phik, float* __restrict__ vt,
    float* __restrict__ beta, float* __restrict__ mixo)
{
    const int bt = blockIdx.x;
    const int b  = bt >> 10;
    const int t  = bt & 1023;
    const int tid = threadIdx.x;
    const int h  = tid >> 4;
    const int i  = tid & 15;

    float inv = expf(-(float)i * (0.0625f * 9.210340371976184f));
    float ang = (float)t * inv;
    float s = sinf(ang), c = cosf(ang);

    const size_t rb = (size_t)bt * NLIN;
    size_t src = rb + (size_t)h * 32;
    float q1 = lin[src + i],        q2 = lin[src + 16 + i];
    float k1 = lin[src + 1024 + i], k2 = lin[src + 1024 + 16 + i];
    float rq1 = q1*c - q2*s, rq2 = q1*s + q2*c;
    float rk1 = k1*c - k2*s, rk2 = k1*s + k2*c;

    size_t dst = (((size_t)b * NH_ + h) * T_ + t) * D_;
    phiq[dst + i]      = (rq1 > 0.f) ? rq1 + 1.f : expf(rq1);
    phiq[dst + 16 + i] = (rq2 > 0.f) ? rq2 + 1.f : expf(rq2);
    phik[dst + i]      = (rk1 > 0.f) ? rk1 + 1.f : expf(rk1);
    phik[dst + 16 + i] = (rk2 > 0.f) ? rk2 + 1.f : expf(rk2);

    {
        int e  = tid * 2;
        int hh = e >> 5, dd = e & 31;
        float2 vv = *(const float2*)(lin + rb + 2048 + e);
        size_t vd = (((size_t)b * NH_ + hh) * T_ + t) * D_ + dd;
        *(float2*)(vt + vd) = vv;
    }

    if (tid < 64) {
        float xv = lin[rb + 3072 + tid] + bbeta[tid];
        float sg = 1.f / (1.f + expf(-xv));
        sg = fminf(fmaxf(sg, 0.85f), 0.9995f);
        int hh = tid >> 1, mm = tid & 1;
        beta[(((size_t)b * NH_ + hh) * M_ + mm) * T_ + t] = sg;
    }
    if (tid < 32) {
        int hh = tid;
        float a0 = lin[rb + 3136 + hh*2]     + bmix[hh*2];
        float a1 = lin[rb + 3136 + hh*2 + 1] + bmix[hh*2 + 1];
        float mx = fmaxf(a0, a1);
        float e0 = expf(a0 - mx), e1 = expf(a1 - mx);
        float rinv = 1.f / (e0 + e1);
        size_t base = (((size_t)b * NH_ + hh) * M_) * T_ + t;
        mixo[base]      = e0 * rinv;
        mixo[base + T_] = e1 * rinv;
    }
}

// ---------------- chunk-local cumprod of beta ----------------
__global__ __launch_bounds__(32) void cumprod_kernel(
    const float* __restrict__ beta, float* __restrict__ P)
{
    const int blk = blockIdx.x;
    const int bhm = blk >> 5, c = blk & 31;
    const int lane = threadIdx.x;
    size_t idx = (size_t)bhm * T_ + c * 32 + lane;
    float v = beta[idx];
#pragma unroll
    for (int o = 1; o < 32; o <<= 1) {
        float u = __shfl_up_sync(0xffffffffu, v, o);
        if (lane >= o) v *= u;
    }
    P[idx] = v;
}

// ---------------- per-chunk U = K~^T V (stored [e][d]) and ksum ----------------
__global__ __launch_bounds__(256) void chunk_sum_kernel(
    const float* __restrict__ phik, const float* __restrict__ vt,
    const float* __restrict__ P, float* __restrict__ U, float* __restrict__ ksum)
{
    const int blk = blockIdx.x;
    const int bhm = blk >> 5, c = blk & 31;
    const int bh  = bhm >> 1;
    const int t0  = c * 32;

    __shared__ float kt[32][33];
    __shared__ float vv[32][33];

    const int tl = threadIdx.x >> 3;
    const int x4 = (threadIdx.x & 7) * 4;

    float Pt  = P[(size_t)bhm * T_ + t0 + tl];
    float inv = 1.f / Pt;
    size_t base = ((size_t)bh * T_ + t0 + tl) * 32 + x4;
    float4 kv = *(const float4*)(phik + base);
    kt[tl][x4+0] = kv.x * inv; kt[tl][x4+1] = kv.y * inv;
    kt[tl][x4+2] = kv.z * inv; kt[tl][x4+3] = kv.w * inv;
    float4 vz = *(const float4*)(vt + base);
    vv[tl][x4+0] = vz.x; vv[tl][x4+1] = vz.y; vv[tl][x4+2] = vz.z; vv[tl][x4+3] = vz.w;
    __syncthreads();

    const int e = tl;
    float a0 = 0.f, a1 = 0.f, a2 = 0.f, a3 = 0.f;
#pragma unroll
    for (int t = 0; t < 32; t++) {
        float ve = vv[t][e];
        a0 = fmaf(kt[t][x4+0], ve, a0);
        a1 = fmaf(kt[t][x4+1], ve, a1);
        a2 = fmaf(kt[t][x4+2], ve, a2);
        a3 = fmaf(kt[t][x4+3], ve, a3);
    }
    *(float4*)(U + (size_t)blk * 1024 + e * 32 + x4) = make_float4(a0, a1, a2, a3);

    if (threadIdx.x < 32) {
        int d = threadIdx.x;
        float s = 0.f;
#pragma unroll
        for (int t = 0; t < 32; t++) s += kt[t][d];
        ksum[(size_t)blk * 32 + d] = s;
    }
}

// ---------------- sequential carry over chunks ----------------
__global__ __launch_bounds__(32) void carry_kernel(
    const float* __restrict__ P, const float* __restrict__ U,
    const float* __restrict__ ksum, float* __restrict__ Scar, float* __restrict__ Kcar)
{
    const int bhm = blockIdx.x;
    const int e = threadIdx.x;
    float S[32];
#pragma unroll
    for (int d = 0; d < 32; d++) S[d] = 0.f;
    float Kv = 0.f;

    for (int c = 0; c < NC_; c++) {
        size_t tb = (size_t)bhm * NC_ + c;
        float* sd = Scar + tb * 1024 + e * 32;
#pragma unroll
        for (int q = 0; q < 8; q++)
            ((float4*)sd)[q] = make_float4(S[4*q], S[4*q+1], S[4*q+2], S[4*q+3]);
        Kcar[tb * 32 + e] = Kv;

        float PL = P[(size_t)bhm * T_ + c * 32 + 31];
        const float* ud = U + tb * 1024 + e * 32;
#pragma unroll
        for (int q = 0; q < 8; q++) {
            float4 u = ((const float4*)ud)[q];
            S[4*q+0] = PL * (S[4*q+0] + u.x);
            S[4*q+1] = PL * (S[4*q+1] + u.y);
            S[4*q+2] = PL * (S[4*q+2] + u.z);
            S[4*q+3] = PL * (S[4*q+3] + u.w);
        }
        Kv = PL * (Kv + ksum[tb * 32 + e]);
    }
}

// ---------------- per-chunk output ----------------
__global__ __launch_bounds__(256) void chunk_out_kernel(
    const float* __restrict__ phiq, const float* __restrict__ phik,
    const float* __restrict__ vt,   const float* __restrict__ P,
    const float* __restrict__ mix,  const float* __restrict__ Scar,
    const float* __restrict__ Kcar, float* __restrict__ y)
{
    const int blk = blockIdx.x;
    const int bh = blk >> 5, c = blk & 31;
    const int t0 = c * 32;

    __shared__ float qt[32][33];
    __shared__ float kt[32][33];
    __shared__ float vv[32][33];
    __shared__ float ST[32][33];
    __shared__ float A [32][33];
    __shared__ float den[32];
    __shared__ float K0[32];

    const int tid = threadIdx.x;
    const int tl = tid >> 3;
    const int x4 = (tid & 7) * 4;
    const int lane = tid & 31, w = tid >> 5;

    size_t vbase = ((size_t)bh * T_ + t0 + tl) * 32 + x4;
    {
        float4 vz = *(const float4*)(vt + vbase);
        vv[tl][x4+0] = vz.x; vv[tl][x4+1] = vz.y; vv[tl][x4+2] = vz.z; vv[tl][x4+3] = vz.w;
    }

    float yac[4] = {0.f, 0.f, 0.f, 0.f};

    for (int m = 0; m < 2; m++) {
        const int bhm = bh * 2 + m;
        float Pt  = P[(size_t)bhm * T_ + t0 + tl];
        float inv = 1.f / Pt;
        float4 qv = *(const float4*)(phiq + vbase);
        float4 kv = *(const float4*)(phik + vbase);
        qt[tl][x4+0] = qv.x * Pt;  qt[tl][x4+1] = qv.y * Pt;
        qt[tl][x4+2] = qv.z * Pt;  qt[tl][x4+3] = qv.w * Pt;
        kt[tl][x4+0] = kv.x * inv; kt[tl][x4+1] = kv.y * inv;
        kt[tl][x4+2] = kv.z * inv; kt[tl][x4+3] = kv.w * inv;

        size_t tb = (size_t)bhm * NC_ + c;
        float4 sv = ((const float4*)(Scar + tb * 1024))[tid];
        ST[tl][x4+0] = sv.x; ST[tl][x4+1] = sv.y; ST[tl][x4+2] = sv.z; ST[tl][x4+3] = sv.w;
        if (tid < 32) K0[tid] = Kcar[tb * 32 + tid];
        __syncthreads();

        float a[4] = {0.f, 0.f, 0.f, 0.f};
#pragma unroll
        for (int d = 0; d < 32; d++) {
            float qd = qt[tl][d];
            a[0] = fmaf(qd, kt[x4+0][d], a[0]);
            a[1] = fmaf(qd, kt[x4+1][d], a[1]);
            a[2] = fmaf(qd, kt[x4+2][d], a[2]);
            a[3] = fmaf(qd, kt[x4+3][d], a[3]);
        }
#pragma unroll
        for (int q = 0; q < 4; q++)
            A[tl][x4+q] = (x4 + q <= tl) ? a[q] : 0.f;
        __syncthreads();

#pragma unroll
        for (int r = 0; r < 4; r++) {
            int t = w * 4 + r;
            float v = A[t][lane] + qt[t][lane] * K0[lane];
#pragma unroll
            for (int o = 16; o > 0; o >>= 1)
                v += __shfl_xor_sync(0xffffffffu, v, o);
            if (lane == 0) den[t] = v + 1e-6f;
        }
        __syncthreads();

        float mixv = mix[(size_t)bhm * T_ + t0 + tl];
        float f = mixv / den[tl];
        float n[4] = {0.f, 0.f, 0.f, 0.f};
#pragma unroll
        for (int j = 0; j < 32; j++) {
            float aj = A[tl][j];
            n[0] = fmaf(aj, vv[j][x4+0], n[0]);
            n[1] = fmaf(aj, vv[j][x4+1], n[1]);
            n[2] = fmaf(aj, vv[j][x4+2], n[2]);
            n[3] = fmaf(aj, vv[j][x4+3], n[3]);
        }
#pragma unroll
        for (int d = 0; d < 32; d++) {
            float qd = qt[tl][d];
            n[0] = fmaf(qd, ST[x4+0][d], n[0]);
            n[1] = fmaf(qd, ST[x4+1][d], n[1]);
            n[2] = fmaf(qd, ST[x4+2][d], n[2]);
            n[3] = fmaf(qd, ST[x4+3][d], n[3]);
        }
#pragma unroll
        for (int q = 0; q < 4; q++) yac[q] = fmaf(f, n[q], yac[q]);
        __syncthreads();
    }

    const int b = bh >> 5, h = bh & 31;
    *(float4*)(y + ((size_t)(b * T_ + t0 + tl)) * H_ + h * 32 + x4)
        = make_float4(yac[0], yac[1], yac[2], yac[3]);
}

// ---------------- LayerNorm ----------------
__global__ __launch_bounds__(256) void ln_kernel(
    const float* __restrict__ z, const float* __restrict__ gamma,
    const float* __restrict__ bta, float* __restrict__ out)
{
    const int row = blockIdx.x;
    const float* zr = z + (size_t)row * H_;
    float s = 0.f, ss = 0.f;
    for (int i = threadIdx.x; i < H_; i += 256) {
        float v = zr[i]; s += v; ss = fmaf(v, v, ss);
    }
    __shared__ float sh[64];
#pragma unroll
    for (int o = 16; o > 0; o >>= 1) {
        s  += __shfl_xor_sync(0xffffffffu, s, o);
        ss += __shfl_xor_sync(0xffffffffu, ss, o);
    }
    int wid = threadIdx.x >> 5, lane = threadIdx.x & 31;
    if (lane == 0) { sh[wid] = s; sh[32 + wid] = ss; }
    __syncthreads();
    if (threadIdx.x < 32) {
        float a = (threadIdx.x < 8) ? sh[threadIdx.x] : 0.f;
        float c = (threadIdx.x < 8) ? sh[32 + threadIdx.x] : 0.f;
#pragma unroll
        for (int o = 4; o > 0; o >>= 1) {
            a += __shfl_xor_sync(0xffffffffu, a, o);
            c += __shfl_xor_sync(0xffffffffu, c, o);
        }
        if (threadIdx.x == 0) { sh[0] = a; sh[1] = c; }
    }
    __syncthreads();
    float mu  = sh[0] * (1.f / H_);
    float var = sh[1] * (1.f / H_) - mu * mu;
    float rstd = rsqrtf(var + 1e-5f);
    for (int i = threadIdx.x; i < H_; i += 256)
        out[(size_t)row * H_ + i] = (zr[i] - mu) * rstd * gamma[i] + bta[i];
}

// ---------------- launch ----------------
extern "C" void kernel_launch(void* const* d_in, const int* in_sizes, int n_in,
                              void* d_out, int out_size)
{
    const float* x     = (const float*)d_in[0];
    const float* Wq    = (const float*)d_in[1];
    const float* Wk    = (const float*)d_in[2];
    const float* Wv    = (const float*)d_in[3];
    const float* Wbeta = (const float*)d_in[4];
    const float* bbeta = (const float*)d_in[5];
    const float* Wmix  = (const float*)d_in[6];
    const float* bmix  = (const float*)d_in[7];
    const float* Wout  = (const float*)d_in[8];
    const float* bout  = (const float*)d_in[9];
    const float* ln_g  = (const float*)d_in[10];
    const float* ln_b  = (const float*)d_in[11];
    float* out = (float*)d_out;

    float *lin,*phiq,*phik,*vt,*beta,*mix,*P,*U,*ksum,*Scar,*Kcar,*ysum,*z;
    cudaGetSymbolAddress((void**)&lin,  g_lin);
    cudaGetSymbolAddress((void**)&phiq, g_phiq);
    cudaGetSymbolAddress((void**)&phik, g_phik);
    cudaGetSymbolAddress((void**)&vt,   g_vt);
    cudaGetSymbolAddress((void**)&beta, g_beta);
    cudaGetSymbolAddress((void**)&mix,  g_mix);
    cudaGetSymbolAddress((void**)&P,    g_P);
    cudaGetSymbolAddress((void**)&U,    g_U);
    cudaGetSymbolAddress((void**)&ksum, g_ksum);
    cudaGetSymbolAddress((void**)&Scar, g_Scar);
    cudaGetSymbolAddress((void**)&Kcar, g_Kcar);
    cudaGetSymbolAddress((void**)&ysum, g_ysum);
    cudaGetSymbolAddress((void**)&z,    g_z);

    cudaFuncSetAttribute(gemm_mma<0>, cudaFuncAttributeMaxDynamicSharedMemorySize, GSMEM_BYTES);
    cudaFuncSetAttribute(gemm_mma<2>, cudaFuncAttributeMaxDynamicSharedMemorySize, GSMEM_BYTES);

    // ---- fused q/k/v/beta/mix projection: one launch, 800 CTAs ----
    gemm_mma<0><<<dim3(NLIN/128, 32), 256, GSMEM_BYTES>>>(
        x, Wq, Wk, Wv, Wbeta, Wmix, lin, nullptr, nullptr);

    prep_kernel<<<B_*T_, 512>>>(lin, bbeta, bmix, phiq, phik, vt, beta, mix);

    cumprod_kernel<<<BHM_*NC_, 32>>>(beta, P);
    chunk_sum_kernel<<<BHM_*NC_, 256>>>(phik, vt, P, U, ksum);
    carry_kernel<<<BHM_, 32>>>(P, U, ksum, Scar, Kcar);
    chunk_out_kernel<<<B_*NH_*NC_, 256>>>(phiq, phik, vt, P, mix, Scar, Kcar, ysum);

    // ---- output projection ----
    gemm_mma<2><<<dim3(8, 32), 256, GSMEM_BYTES>>>(
        ysum, Wout, nullptr, nullptr, nullptr, nullptr, z, bout, x);

    ln_kernel<<<B_*T_, 256>>>(z, ln_g, ln_b, out);
}

// round 10
// speedup vs baseline: 1.8232x; 1.3921x over previous
#include <cuda_runtime.h>
#include <math.h>
#include <stdint.h>

#define B_  4
#define T_  1024
#define H_  1024
#define NH_ 32
#define D_  32
#define M_  2
#define K_  1024
#define NC_ 32
#define BHM_ (B_*NH_*M_)
#define NLIN 3200          // q(1024) k(1024) v(1024) beta(64) mix(64)
#define WROWS 4224         // + Wout rows at 3200

// ---------------- scratch ----------------
__device__ __align__(16) uint32_t g_xpk [B_*T_*K_];
__device__ __align__(16) uint32_t g_wpk [(size_t)WROWS*K_];
__device__ __align__(16) uint32_t g_ypk [B_*T_*H_];
__device__ float g_lin [(size_t)B_*T_*NLIN];
__device__ float g_phiq [B_*T_*H_];   // [b,h,t,d]
__device__ float g_phik [B_*T_*H_];
__device__ float g_vt   [B_*T_*H_];
__device__ float g_beta [BHM_*T_];
__device__ float g_mix  [BHM_*T_];
__device__ float g_P    [BHM_*T_];
__device__ float g_U    [(size_t)BHM_*NC_*1024];
__device__ float g_ksum [BHM_*NC_*32];
__device__ float g_Scar [(size_t)BHM_*NC_*1024];
__device__ float g_Kcar [BHM_*NC_*32];
__device__ float g_z    [B_*T_*H_];

// ==================== helpers ====================
__device__ __forceinline__ uint32_t smem_u32(const void* p) {
    uint32_t a;
    asm("{ .reg .u64 t; cvta.to.shared.u64 t, %1; cvt.u32.u64 %0, t; }" : "=r"(a) : "l"(p));
    return a;
}
__device__ __forceinline__ void cp_async16(uint32_t dst, const void* src) {
    asm volatile("cp.async.ca.shared.global [%0], [%1], 16;" :: "r"(dst), "l"(src));
}
__device__ __forceinline__ void cp_commit() { asm volatile("cp.async.commit_group;"); }
template<int N> __device__ __forceinline__ void cp_wait() {
    asm volatile("cp.async.wait_group %0;" :: "n"(N));
}

// pack fp32 -> (bf16_lo << 16) | bf16_hi, hi+lo ~= x to ~2^-16 rel
__device__ __forceinline__ uint32_t packbf(float x) {
    unsigned short h, l;
    asm("cvt.rn.bf16.f32 %0, %1;" : "=h"(h) : "f"(x));
    float hf = __uint_as_float(((uint32_t)h) << 16);
    asm("cvt.rn.bf16.f32 %0, %1;" : "=h"(l) : "f"(x - hf));
    return ((uint32_t)l << 16) | (uint32_t)h;
}

__device__ __forceinline__ void ldmx4(uint32_t* r, uint32_t addr) {
    asm volatile("ldmatrix.sync.aligned.m8n8.x4.shared.b16 {%0,%1,%2,%3}, [%4];"
        : "=r"(r[0]), "=r"(r[1]), "=r"(r[2]), "=r"(r[3]) : "r"(addr));
}

__device__ __forceinline__ void mma_bf16(float* c, const uint32_t* a, const uint32_t* b) {
    asm volatile("mma.sync.aligned.m16n8k16.row.col.f32.bf16.bf16.f32 "
        "{%0,%1,%2,%3}, {%4,%5,%6,%7}, {%8,%9}, {%0,%1,%2,%3};"
        : "+f"(c[0]), "+f"(c[1]), "+f"(c[2]), "+f"(c[3])
        : "r"(a[0]), "r"(a[1]), "r"(a[2]), "r"(a[3]), "r"(b[0]), "r"(b[1]));
}

__device__ __forceinline__ uint32_t hswap(uint32_t x) {
    uint32_t r;
    asm("prmt.b32 %0, %1, %1, 0x1032;" : "=r"(r) : "r"(x));
    return r;
}

// ---------------- fp32 -> packed bf16 split ----------------
__global__ __launch_bounds__(256) void split_kernel(
    const float* __restrict__ src, uint32_t* __restrict__ dst, int n4)
{
    int i = blockIdx.x * 256 + threadIdx.x;
    if (i >= n4) return;
    float4 v = ((const float4*)src)[i];
    uint4 o;
    o.x = packbf(v.x); o.y = packbf(v.y); o.z = packbf(v.z); o.w = packbf(v.w);
    ((uint4*)dst)[i] = o;
}

// ==================== packed-bf16 double GEMM ====================
// C[M,N] = A.B^T over packed bf16 pairs. CTA 128x128, KC=16 orig-k per stage,
// 3 stages, 2 CTAs/SM. Pass1 = hi.hi+lo.lo, pass2 (B halfword-swapped) = cross terms.
// MODE 0: -> lin (ldc=NLIN). MODE 2: + bias + residual (ldc=H_).

#define SSLICE 6144                  // bytes per 128-row x 48B sub-slice
#define ASTG   (2*SSLICE)            // 12288 bytes per stage per matrix
#define BREG   (3*ASTG)              // 36864: B region base
#define GSMEM_BYTES (6*ASTG)         // 73728

template<int MODE>
__global__ void __launch_bounds__(256, 2) gemm_bf(
    const uint32_t* __restrict__ Apk, const uint32_t* __restrict__ Bpk,
    float* __restrict__ C, const float* __restrict__ bias, const float* __restrict__ xres)
{
    extern __shared__ uint32_t sm[];
    const uint32_t sa = smem_u32(sm);
    const int tid  = threadIdx.x;
    const int row0 = blockIdx.y * 128;
    const int col0 = blockIdx.x * 128;
    const int lane = tid & 31;
    const int wm = ((tid >> 7) & 1) * 64;
    const int wn = ((tid >> 5) & 3) * 32;

    const int ldrow = tid >> 1;
    const int half  = tid & 1;
    const uint32_t dsto = (uint32_t)(ldrow * 48 + half * 16);
    const uint32_t* asrc = Apk + (size_t)(row0 + ldrow) * K_ + half * 4;
    const uint32_t* bsrc = Bpk + (size_t)(col0 + ldrow) * K_ + half * 4;

#define ISSUE(chunk, stg) do { \
    const uint32_t* _ap = asrc + (chunk) * 16; \
    const uint32_t* _bp = bsrc + (chunk) * 16; \
    uint32_t _a = sa + (uint32_t)(stg) * ASTG + dsto; \
    cp_async16(_a,                 _ap); \
    cp_async16(_a + SSLICE,        _ap + 8); \
    cp_async16(_a + BREG,          _bp); \
    cp_async16(_a + BREG + SSLICE, _bp + 8); \
    cp_commit(); } while (0)

    ISSUE(0, 0); ISSUE(1, 1); ISSUE(2, 2);

    // ldmatrix per-thread byte offsets (48B row stride, conflict-free phases)
    uint32_t aoff[4], boff[2];
#pragma unroll
    for (int mt = 0; mt < 4; mt++)
        aoff[mt] = (uint32_t)((wm + mt * 16 + (lane & 15)) * 48 + ((lane >> 4) << 4));
#pragma unroll
    for (int p = 0; p < 2; p++)
        boff[p] = (uint32_t)((wn + p * 16 + (lane & 7) + ((lane >> 4) << 3)) * 48
                             + (((lane >> 3) & 1) << 4));

    float cc[64];
#pragma unroll
    for (int x = 0; x < 64; x++) cc[x] = 0.f;

    int stg = 0;
    for (int i = 0; i < 64; i++) {
        if (i <= 61)      cp_wait<2>();
        else if (i == 62) cp_wait<1>();
        else              cp_wait<0>();
        __syncthreads();
        const uint32_t Ab = sa + (uint32_t)stg * ASTG;
        const uint32_t Bb = Ab + BREG;

#pragma unroll
        for (int s = 0; s < 2; s++) {
            const uint32_t Asl = Ab + s * SSLICE;
            const uint32_t Bsl = Bb + s * SSLICE;
            uint32_t a[16], b[8];
#pragma unroll
            for (int mt = 0; mt < 4; mt++) ldmx4(a + mt * 4, Asl + aoff[mt]);
#pragma unroll
            for (int p = 0; p < 2; p++)  ldmx4(b + p * 4, Bsl + boff[p]);
            // pass 1: hi.hi + lo.lo
#pragma unroll
            for (int mt = 0; mt < 4; mt++)
#pragma unroll
            for (int nt = 0; nt < 4; nt++)
                mma_bf16(&cc[(mt*4+nt)*4], &a[mt*4], &b[nt*2]);
            // pass 2: cross terms via halfword swap of B
            uint32_t bs[8];
#pragma unroll
            for (int j = 0; j < 8; j++) bs[j] = hswap(b[j]);
#pragma unroll
            for (int mt = 0; mt < 4; mt++)
#pragma unroll
            for (int nt = 0; nt < 4; nt++)
                mma_bf16(&cc[(mt*4+nt)*4], &a[mt*4], &bs[nt*2]);
        }
        __syncthreads();
        if (i + 3 < 64) ISSUE(i + 3, stg);
        stg = (stg == 2) ? 0 : stg + 1;
    }

    // ---- epilogue ----
    const int ldc = (MODE == 0) ? NLIN : H_;
#pragma unroll
    for (int mt = 0; mt < 4; mt++)
#pragma unroll
    for (int nt = 0; nt < 4; nt++) {
        const int r = row0 + wm + mt * 16 + (lane >> 2);
        const int c = col0 + wn + nt * 8 + (lane & 3) * 2;
        float* p = &cc[(mt*4+nt)*4];
        if (MODE == 0) {
            *(float2*)&C[(size_t)r * ldc + c]     = make_float2(p[0], p[1]);
            *(float2*)&C[(size_t)(r+8) * ldc + c] = make_float2(p[2], p[3]);
        } else {
            const size_t o0 = (size_t)r * ldc + c, o1 = (size_t)(r+8) * ldc + c;
            float2 x0 = *(const float2*)&xres[o0];
            float2 x1 = *(const float2*)&xres[o1];
            float2 bv = *(const float2*)&bias[c];
            *(float2*)&C[o0] = make_float2(p[0] + bv.x + x0.x, p[1] + bv.y + x0.y);
            *(float2*)&C[o1] = make_float2(p[2] + bv.x + x1.x, p[3] + bv.y + x1.y);
        }
    }
#undef ISSUE
}

// ---------------- prep: RoPE + phi, beta, mix, v transpose (reads g_lin) ----------------
__global__ __launch_bounds__(512) void prep_kernel(
    const float* __restrict__ lin, const float* __restrict__ bbeta,
    const float* __restrict__ bmix,
    float* __restrict__ phiq, float* __restrict__ phik, float* __restrict__ vt,
    float* __restrict__ beta, float* __restrict__ mixo)
{
    const int bt = blockIdx.x;
    const int b  = bt >> 10;
    const int t  = bt & 1023;
    const int tid = threadIdx.x;
    const int h  = tid >> 4;
    const int i  = tid & 15;

    float inv = expf(-(float)i * (0.0625f * 9.210340371976184f));
    float ang = (float)t * inv;
    float s = sinf(ang), c = cosf(ang);

    const size_t rb = (size_t)bt * NLIN;
    size_t src = rb + (size_t)h * 32;
    float q1 = lin[src + i],        q2 = lin[src + 16 + i];
    float k1 = lin[src + 1024 + i], k2 = lin[src + 1024 + 16 + i];
    float rq1 = q1*c - q2*s, rq2 = q1*s + q2*c;
    float rk1 = k1*c - k2*s, rk2 = k1*s + k2*c;

    size_t dst = (((size_t)b * NH_ + h) * T_ + t) * D_;
    phiq[dst + i]      = (rq1 > 0.f) ? rq1 + 1.f : expf(rq1);
    phiq[dst + 16 + i] = (rq2 > 0.f) ? rq2 + 1.f : expf(rq2);
    phik[dst + i]      = (rk1 > 0.f) ? rk1 + 1.f : expf(rk1);
    phik[dst + 16 + i] = (rk2 > 0.f) ? rk2 + 1.f : expf(rk2);

    {
        int e  = tid * 2;
        int hh = e >> 5, dd = e & 31;
        float2 vv = *(const float2*)(lin + rb + 2048 + e);
        size_t vd = (((size_t)b * NH_ + hh) * T_ + t) * D_ + dd;
        *(float2*)(vt + vd) = vv;
    }

    if (tid < 64) {
        float xv = lin[rb + 3072 + tid] + bbeta[tid];
        float sg = 1.f / (1.f + expf(-xv));
        sg = fminf(fmaxf(sg, 0.85f), 0.9995f);
        int hh = tid >> 1, mm = tid & 1;
        beta[(((size_t)b * NH_ + hh) * M_ + mm) * T_ + t] = sg;
    }
    if (tid < 32) {
        int hh = tid;
        float a0 = lin[rb + 3136 + hh*2]     + bmix[hh*2];
        float a1 = lin[rb + 3136 + hh*2 + 1] + bmix[hh*2 + 1];
        float mx = fmaxf(a0, a1);
        float e0 = expf(a0 - mx), e1 = expf(a1 - mx);
        float rinv = 1.f / (e0 + e1);
        size_t base = (((size_t)b * NH_ + hh) * M_) * T_ + t;
        mixo[base]      = e0 * rinv;
        mixo[base + T_] = e1 * rinv;
    }
}

// ---------------- chunk-local cumprod of beta ----------------
__global__ __launch_bounds__(32) void cumprod_kernel(
    const float* __restrict__ beta, float* __restrict__ P)
{
    const int blk = blockIdx.x;
    const int bhm = blk >> 5, c = blk & 31;
    const int lane = threadIdx.x;
    size_t idx = (size_t)bhm * T_ + c * 32 + lane;
    float v = beta[idx];
#pragma unroll
    for (int o = 1; o < 32; o <<= 1) {
        float u = __shfl_up_sync(0xffffffffu, v, o);
        if (lane >= o) v *= u;
    }
    P[idx] = v;
}

// ---------------- per-chunk U = K~^T V (stored [e][d]) and ksum ----------------
__global__ __launch_bounds__(256) void chunk_sum_kernel(
    const float* __restrict__ phik, const float* __restrict__ vt,
    const float* __restrict__ P, float* __restrict__ U, float* __restrict__ ksum)
{
    const int blk = blockIdx.x;
    const int bhm = blk >> 5, c = blk & 31;
    const int bh  = bhm >> 1;
    const int t0  = c * 32;

    __shared__ float kt[32][33];
    __shared__ float vv[32][33];

    const int tl = threadIdx.x >> 3;
    const int x4 = (threadIdx.x & 7) * 4;

    float Pt  = P[(size_t)bhm * T_ + t0 + tl];
    float inv = 1.f / Pt;
    size_t base = ((size_t)bh * T_ + t0 + tl) * 32 + x4;
    float4 kv = *(const float4*)(phik + base);
    kt[tl][x4+0] = kv.x * inv; kt[tl][x4+1] = kv.y * inv;
    kt[tl][x4+2] = kv.z * inv; kt[tl][x4+3] = kv.w * inv;
    float4 vz = *(const float4*)(vt + base);
    vv[tl][x4+0] = vz.x; vv[tl][x4+1] = vz.y; vv[tl][x4+2] = vz.z; vv[tl][x4+3] = vz.w;
    __syncthreads();

    const int e = tl;
    float a0 = 0.f, a1 = 0.f, a2 = 0.f, a3 = 0.f;
#pragma unroll
    for (int t = 0; t < 32; t++) {
        float ve = vv[t][e];
        a0 = fmaf(kt[t][x4+0], ve, a0);
        a1 = fmaf(kt[t][x4+1], ve, a1);
        a2 = fmaf(kt[t][x4+2], ve, a2);
        a3 = fmaf(kt[t][x4+3], ve, a3);
    }
    *(float4*)(U + (size_t)blk * 1024 + e * 32 + x4) = make_float4(a0, a1, a2, a3);

    if (threadIdx.x < 32) {
        int d = threadIdx.x;
        float s = 0.f;
#pragma unroll
        for (int t = 0; t < 32; t++) s += kt[t][d];
        ksum[(size_t)blk * 32 + d] = s;
    }
}

// ---------------- sequential carry over chunks ----------------
__global__ __launch_bounds__(32) void carry_kernel(
    const float* __restrict__ P, const float* __restrict__ U,
    const float* __restrict__ ksum, float* __restrict__ Scar, float* __restrict__ Kcar)
{
    const int bhm = blockIdx.x;
    const int e = threadIdx.x;
    float S[32];
#pragma unroll
    for (int d = 0; d < 32; d++) S[d] = 0.f;
    float Kv = 0.f;

    for (int c = 0; c < NC_; c++) {
        size_t tb = (size_t)bhm * NC_ + c;
        float* sd = Scar + tb * 1024 + e * 32;
#pragma unroll
        for (int q = 0; q < 8; q++)
            ((float4*)sd)[q] = make_float4(S[4*q], S[4*q+1], S[4*q+2], S[4*q+3]);
        Kcar[tb * 32 + e] = Kv;

        float PL = P[(size_t)bhm * T_ + c * 32 + 31];
        const float* ud = U + tb * 1024 + e * 32;
#pragma unroll
        for (int q = 0; q < 8; q++) {
            float4 u = ((const float4*)ud)[q];
            S[4*q+0] = PL * (S[4*q+0] + u.x);
            S[4*q+1] = PL * (S[4*q+1] + u.y);
            S[4*q+2] = PL * (S[4*q+2] + u.z);
            S[4*q+3] = PL * (S[4*q+3] + u.w);
        }
        Kv = PL * (Kv + ksum[tb * 32 + e]);
    }
}

// ---------------- per-chunk output (writes packed bf16 y) ----------------
__global__ __launch_bounds__(256) void chunk_out_kernel(
    const float* __restrict__ phiq, const float* __restrict__ phik,
    const float* __restrict__ vt,   const float* __restrict__ P,
    const float* __restrict__ mix,  const float* __restrict__ Scar,
    const float* __restrict__ Kcar, uint32_t* __restrict__ ypk)
{
    const int blk = blockIdx.x;
    const int bh = blk >> 5, c = blk & 31;
    const int t0 = c * 32;

    __shared__ float qt[32][33];
    __shared__ float kt[32][33];
    __shared__ float vv[32][33];
    __shared__ float ST[32][33];
    __shared__ float A [32][33];
    __shared__ float den[32];
    __shared__ float K0[32];

    const int tid = threadIdx.x;
    const int tl = tid >> 3;
    const int x4 = (tid & 7) * 4;
    const int lane = tid & 31, w = tid >> 5;

    size_t vbase = ((size_t)bh * T_ + t0 + tl) * 32 + x4;
    {
        float4 vz = *(const float4*)(vt + vbase);
        vv[tl][x4+0] = vz.x; vv[tl][x4+1] = vz.y; vv[tl][x4+2] = vz.z; vv[tl][x4+3] = vz.w;
    }

    float yac[4] = {0.f, 0.f, 0.f, 0.f};

    for (int m = 0; m < 2; m++) {
        const int bhm = bh * 2 + m;
        float Pt  = P[(size_t)bhm * T_ + t0 + tl];
        float inv = 1.f / Pt;
        float4 qv = *(const float4*)(phiq + vbase);
        float4 kv = *(const float4*)(phik + vbase);
        qt[tl][x4+0] = qv.x * Pt;  qt[tl][x4+1] = qv.y * Pt;
        qt[tl][x4+2] = qv.z * Pt;  qt[tl][x4+3] = qv.w * Pt;
        kt[tl][x4+0] = kv.x * inv; kt[tl][x4+1] = kv.y * inv;
        kt[tl][x4+2] = kv.z * inv; kt[tl][x4+3] = kv.w * inv;

        size_t tb = (size_t)bhm * NC_ + c;
        float4 sv = ((const float4*)(Scar + tb * 1024))[tid];
        ST[tl][x4+0] = sv.x; ST[tl][x4+1] = sv.y; ST[tl][x4+2] = sv.z; ST[tl][x4+3] = sv.w;
        if (tid < 32) K0[tid] = Kcar[tb * 32 + tid];
        __syncthreads();

        float a[4] = {0.f, 0.f, 0.f, 0.f};
#pragma unroll
        for (int d = 0; d < 32; d++) {
            float qd = qt[tl][d];
            a[0] = fmaf(qd, kt[x4+0][d], a[0]);
            a[1] = fmaf(qd, kt[x4+1][d], a[1]);
            a[2] = fmaf(qd, kt[x4+2][d], a[2]);
            a[3] = fmaf(qd, kt[x4+3][d], a[3]);
        }
#pragma unroll
        for (int q = 0; q < 4; q++)
            A[tl][x4+q] = (x4 + q <= tl) ? a[q] : 0.f;
        __syncthreads();

#pragma unroll
        for (int r = 0; r < 4; r++) {
            int t = w * 4 + r;
            float v = A[t][lane] + qt[t][lane] * K0[lane];
#pragma unroll
            for (int o = 16; o > 0; o >>= 1)
                v += __shfl_xor_sync(0xffffffffu, v, o);
            if (lane == 0) den[t] = v + 1e-6f;
        }
        __syncthreads();

        float mixv = mix[(size_t)bhm * T_ + t0 + tl];
        float f = mixv / den[tl];
        float n[4] = {0.f, 0.f, 0.f, 0.f};
#pragma unroll
        for (int j = 0; j < 32; j++) {
            float aj = A[tl][j];
            n[0] = fmaf(aj, vv[j][x4+0], n[0]);
            n[1] = fmaf(aj, vv[j][x4+1], n[1]);
            n[2] = fmaf(aj, vv[j][x4+2], n[2]);
            n[3] = fmaf(aj, vv[j][x4+3], n[3]);
        }
#pragma unroll
        for (int d = 0; d < 32; d++) {
            float qd = qt[tl][d];
            n[0] = fmaf(qd, ST[x4+0][d], n[0]);
            n[1] = fmaf(qd, ST[x4+1][d], n[1]);
            n[2] = fmaf(qd, ST[x4+2][d], n[2]);
            n[3] = fmaf(qd, ST[x4+3][d], n[3]);
        }
#pragma unroll
        for (int q = 0; q < 4; q++) yac[q] = fmaf(f, n[q], yac[q]);
        __syncthreads();
    }

    const int b = bh >> 5, h = bh & 31;
    uint4 pk;
    pk.x = packbf(yac[0]); pk.y = packbf(yac[1]);
    pk.z = packbf(yac[2]); pk.w = packbf(yac[3]);
    *(uint4*)(ypk + ((size_t)(b * T_ + t0 + tl)) * H_ + h * 32 + x4) = pk;
}

// ---------------- LayerNorm ----------------
__global__ __launch_bounds__(256) void ln_kernel(
    const float* __restrict__ z, const float* __restrict__ gamma,
    const float* __restrict__ bta, float* __restrict__ out)
{
    const int row = blockIdx.x;
    const float* zr = z + (size_t)row * H_;
    float s = 0.f, ss = 0.f;
    for (int i = threadIdx.x; i < H_; i += 256) {
        float v = zr[i]; s += v; ss = fmaf(v, v, ss);
    }
    __shared__ float sh[64];
#pragma unroll
    for (int o = 16; o > 0; o >>= 1) {
        s  += __shfl_xor_sync(0xffffffffu, s, o);
        ss += __shfl_xor_sync(0xffffffffu, ss, o);
    }
    int wid = threadIdx.x >> 5, lane = threadIdx.x & 31;
    if (lane == 0) { sh[wid] = s; sh[32 + wid] = ss; }
    __syncthreads();
    if (threadIdx.x < 32) {
        float a = (threadIdx.x < 8) ? sh[threadIdx.x] : 0.f;
        float c = (threadIdx.x < 8) ? sh[32 + threadIdx.x] : 0.f;
#pragma unroll
        for (int o = 4; o > 0; o >>= 1) {
            a += __shfl_xor_sync(0xffffffffu, a, o);
            c += __shfl_xor_sync(0xffffffffu, c, o);
        }
        if (threadIdx.x == 0) { sh[0] = a; sh[1] = c; }
    }
    __syncthreads();
    float mu  = sh[0] * (1.f / H_);
    float var = sh[1] * (1.f / H_) - mu * mu;
    float rstd = rsqrtf(var + 1e-5f);
    for (int i = threadIdx.x; i < H_; i += 256)
        out[(size_t)row * H_ + i] = (zr[i] - mu) * rstd * gamma[i] + bta[i];
}

// ---------------- launch ----------------
extern "C" void kernel_launch(void* const* d_in, const int* in_sizes, int n_in,
                              void* d_out, int out_size)
{
    const float* x     = (const float*)d_in[0];
    const float* Wq    = (const float*)d_in[1];
    const float* Wk    = (const float*)d_in[2];
    const float* Wv    = (const float*)d_in[3];
    const float* Wbeta = (const float*)d_in[4];
    const float* bbeta = (const float*)d_in[5];
    const float* Wmix  = (const float*)d_in[6];
    const float* bmix  = (const float*)d_in[7];
    const float* Wout  = (const float*)d_in[8];
    const float* bout  = (const float*)d_in[9];
    const float* ln_g  = (const float*)d_in[10];
    const float* ln_b  = (const float*)d_in[11];
    float* out = (float*)d_out;

    uint32_t *xpk,*wpk,*ypk;
    float *lin,*phiq,*phik,*vt,*beta,*mix,*P,*U,*ksum,*Scar,*Kcar,*z;
    cudaGetSymbolAddress((void**)&xpk,  g_xpk);
    cudaGetSymbolAddress((void**)&wpk,  g_wpk);
    cudaGetSymbolAddress((void**)&ypk,  g_ypk);
    cudaGetSymbolAddress((void**)&lin,  g_lin);
    cudaGetSymbolAddress((void**)&phiq, g_phiq);
    cudaGetSymbolAddress((void**)&phik, g_phik);
    cudaGetSymbolAddress((void**)&vt,   g_vt);
    cudaGetSymbolAddress((void**)&beta, g_beta);
    cudaGetSymbolAddress((void**)&mix,  g_mix);
    cudaGetSymbolAddress((void**)&P,    g_P);
    cudaGetSymbolAddress((void**)&U,    g_U);
    cudaGetSymbolAddress((void**)&ksum, g_ksum);
    cudaGetSymbolAddress((void**)&Scar, g_Scar);
    cudaGetSymbolAddress((void**)&Kcar, g_Kcar);
    cudaGetSymbolAddress((void**)&z,    g_z);

    cudaFuncSetAttribute(gemm_bf<0>, cudaFuncAttributeMaxDynamicSharedMemorySize, GSMEM_BYTES);
    cudaFuncSetAttribute(gemm_bf<2>, cudaFuncAttributeMaxDynamicSharedMemorySize, GSMEM_BYTES);

    // ---- pack operands (same byte volume as fp32) ----
    split_kernel<<<4096, 256>>>(x,     xpk, (B_*T_*K_)/4);
    split_kernel<<<1024, 256>>>(Wq,    wpk,                       (1024*K_)/4);
    split_kernel<<<1024, 256>>>(Wk,    wpk + (size_t)1024*K_,     (1024*K_)/4);
    split_kernel<<<1024, 256>>>(Wv,    wpk + (size_t)2048*K_,     (1024*K_)/4);
    split_kernel<<<64,   256>>>(Wbeta, wpk + (size_t)3072*K_,     (64*K_)/4);
    split_kernel<<<64,   256>>>(Wmix,  wpk + (size_t)3136*K_,     (64*K_)/4);
    split_kernel<<<1024, 256>>>(Wout,  wpk + (size_t)3200*K_,     (1024*K_)/4);

    // ---- fused q/k/v/beta/mix projection ----
    gemm_bf<0><<<dim3(NLIN/128, 32), 256, GSMEM_BYTES>>>(xpk, wpk, lin, nullptr, nullptr);

    prep_kernel<<<B_*T_, 512>>>(lin, bbeta, bmix, phiq, phik, vt, beta, mix);

    cumprod_kernel<<<BHM_*NC_, 32>>>(beta, P);
    chunk_sum_kernel<<<BHM_*NC_, 256>>>(phik, vt, P, U, ksum);
    carry_kernel<<<BHM_, 32>>>(P, U, ksum, Scar, Kcar);
    chunk_out_kernel<<<B_*NH_*NC_, 256>>>(phiq, phik, vt, P, mix, Scar, Kcar, ypk);

    // ---- output projection ----
    gemm_bf<2><<<dim3(8, 32), 256, GSMEM_BYTES>>>(ypk, wpk + (size_t)3200*K_, z, bout, x);

    ln_kernel<<<B_*T_, 256>>>(z, ln_g, ln_b, out);
}

// round 11
// speedup vs baseline: 1.9131x; 1.0493x over previous
#include <cuda_runtime.h>
#include <math.h>
#include <stdint.h>

#define B_  4
#define T_  1024
#define H_  1024
#define NH_ 32
#define D_  32
#define M_  2
#define K_  1024
#define NC_ 32
#define BHM_ (B_*NH_*M_)
#define NLIN 3200          // q(1024) k(1024) v(1024) beta(64) mix(64)
#define WROWS 4224         // + Wout rows at 3200

// ---------------- scratch ----------------
__device__ __align__(16) uint32_t g_xpk [B_*T_*K_];
__device__ __align__(16) uint32_t g_wpk [(size_t)WROWS*K_];
__device__ __align__(16) uint32_t g_ypk [B_*T_*H_];
__device__ float g_lin [(size_t)B_*T_*NLIN];
__device__ float g_phiq [B_*T_*H_];   // [b,h,t,d]
__device__ float g_phik [B_*T_*H_];
__device__ float g_vt   [B_*T_*H_];
__device__ float g_beta [BHM_*T_];
__device__ float g_mix  [BHM_*T_];
__device__ float g_P    [BHM_*T_];
__device__ float g_Scar [(size_t)BHM_*NC_*1024];
__device__ float g_Kcar [BHM_*NC_*32];
__device__ float g_z    [B_*T_*H_];

// ==================== helpers ====================
__device__ __forceinline__ uint32_t smem_u32(const void* p) {
    uint32_t a;
    asm("{ .reg .u64 t; cvta.to.shared.u64 t, %1; cvt.u32.u64 %0, t; }" : "=r"(a) : "l"(p));
    return a;
}
__device__ __forceinline__ void cp_async16(uint32_t dst, const void* src) {
    asm volatile("cp.async.ca.shared.global [%0], [%1], 16;" :: "r"(dst), "l"(src));
}
__device__ __forceinline__ void cp_commit() { asm volatile("cp.async.commit_group;"); }
template<int N> __device__ __forceinline__ void cp_wait() {
    asm volatile("cp.async.wait_group %0;" :: "n"(N));
}

// pack fp32 -> (bf16_lo << 16) | bf16_hi, hi+lo ~= x to ~2^-16 rel
__device__ __forceinline__ uint32_t packbf(float x) {
    unsigned short h, l;
    asm("cvt.rn.bf16.f32 %0, %1;" : "=h"(h) : "f"(x));
    float hf = __uint_as_float(((uint32_t)h) << 16);
    asm("cvt.rn.bf16.f32 %0, %1;" : "=h"(l) : "f"(x - hf));
    return ((uint32_t)l << 16) | (uint32_t)h;
}

__device__ __forceinline__ void ldmx4(uint32_t* r, uint32_t addr) {
    asm volatile("ldmatrix.sync.aligned.m8n8.x4.shared.b16 {%0,%1,%2,%3}, [%4];"
        : "=r"(r[0]), "=r"(r[1]), "=r"(r[2]), "=r"(r[3]) : "r"(addr));
}

__device__ __forceinline__ void mma_bf16(float* c, const uint32_t* a, const uint32_t* b) {
    asm volatile("mma.sync.aligned.m16n8k16.row.col.f32.bf16.bf16.f32 "
        "{%0,%1,%2,%3}, {%4,%5,%6,%7}, {%8,%9}, {%0,%1,%2,%3};"
        : "+f"(c[0]), "+f"(c[1]), "+f"(c[2]), "+f"(c[3])
        : "r"(a[0]), "r"(a[1]), "r"(a[2]), "r"(a[3]), "r"(b[0]), "r"(b[1]));
}

__device__ __forceinline__ uint32_t hswap(uint32_t x) {
    uint32_t r;
    asm("prmt.b32 %0, %1, %1, 0x1032;" : "=r"(r) : "r"(x));
    return r;
}

// ---------------- fp32 -> packed bf16 split (x / y) ----------------
__global__ __launch_bounds__(256) void split_kernel(
    const float* __restrict__ src, uint32_t* __restrict__ dst, int n4)
{
    int i = blockIdx.x * 256 + threadIdx.x;
    if (i >= n4) return;
    float4 v = ((const float4*)src)[i];
    uint4 o;
    o.x = packbf(v.x); o.y = packbf(v.y); o.z = packbf(v.z); o.w = packbf(v.w);
    ((uint4*)dst)[i] = o;
}

// ---------------- all-weights split (one launch) ----------------
__global__ __launch_bounds__(256) void split_w_kernel(
    const float* __restrict__ Wq, const float* __restrict__ Wk,
    const float* __restrict__ Wv, const float* __restrict__ Wbeta,
    const float* __restrict__ Wmix, const float* __restrict__ Wout,
    uint32_t* __restrict__ wpk)
{
    int i = blockIdx.x * 256 + threadIdx.x;   // float4 index over 4224*256
    int row = i >> 8;
    const float* src; int r;
    if (row < 1024)      { src = Wq;    r = row; }
    else if (row < 2048) { src = Wk;    r = row - 1024; }
    else if (row < 3072) { src = Wv;    r = row - 2048; }
    else if (row < 3136) { src = Wbeta; r = row - 3072; }
    else if (row < 3200) { src = Wmix;  r = row - 3136; }
    else                 { src = Wout;  r = row - 3200; }
    float4 v = ((const float4*)src)[(size_t)r * 256 + (i & 255)];
    uint4 o;
    o.x = packbf(v.x); o.y = packbf(v.y); o.z = packbf(v.z); o.w = packbf(v.w);
    ((uint4*)wpk)[i] = o;
}

// ==================== packed-bf16 double GEMM ====================
#define SSLICE 6144
#define ASTG   (2*SSLICE)
#define BREG   (3*ASTG)
#define GSMEM_BYTES (6*ASTG)         // 73728

template<int MODE>
__global__ void __launch_bounds__(256, 2) gemm_bf(
    const uint32_t* __restrict__ Apk, const uint32_t* __restrict__ Bpk,
    float* __restrict__ C, const float* __restrict__ bias, const float* __restrict__ xres)
{
    extern __shared__ uint32_t sm[];
    const uint32_t sa = smem_u32(sm);
    const int tid  = threadIdx.x;
    const int row0 = blockIdx.y * 128;
    const int col0 = blockIdx.x * 128;
    const int lane = tid & 31;
    const int wm = ((tid >> 7) & 1) * 64;
    const int wn = ((tid >> 5) & 3) * 32;

    const int ldrow = tid >> 1;
    const int half  = tid & 1;
    const uint32_t dsto = (uint32_t)(ldrow * 48 + half * 16);
    const uint32_t* asrc = Apk + (size_t)(row0 + ldrow) * K_ + half * 4;
    const uint32_t* bsrc = Bpk + (size_t)(col0 + ldrow) * K_ + half * 4;

#define ISSUE(chunk, stg) do { \
    const uint32_t* _ap = asrc + (chunk) * 16; \
    const uint32_t* _bp = bsrc + (chunk) * 16; \
    uint32_t _a = sa + (uint32_t)(stg) * ASTG + dsto; \
    cp_async16(_a,                 _ap); \
    cp_async16(_a + SSLICE,        _ap + 8); \
    cp_async16(_a + BREG,          _bp); \
    cp_async16(_a + BREG + SSLICE, _bp + 8); \
    cp_commit(); } while (0)

    ISSUE(0, 0); ISSUE(1, 1); ISSUE(2, 2);

    uint32_t aoff[4], boff[2];
#pragma unroll
    for (int mt = 0; mt < 4; mt++)
        aoff[mt] = (uint32_t)((wm + mt * 16 + (lane & 15)) * 48 + ((lane >> 4) << 4));
#pragma unroll
    for (int p = 0; p < 2; p++)
        boff[p] = (uint32_t)((wn + p * 16 + (lane & 7) + ((lane >> 4) << 3)) * 48
                             + (((lane >> 3) & 1) << 4));

    float cc[64];
#pragma unroll
    for (int x = 0; x < 64; x++) cc[x] = 0.f;

    int stg = 0;
    for (int i = 0; i < 64; i++) {
        if (i <= 61)      cp_wait<2>();
        else if (i == 62) cp_wait<1>();
        else              cp_wait<0>();
        __syncthreads();
        const uint32_t Ab = sa + (uint32_t)stg * ASTG;
        const uint32_t Bb = Ab + BREG;

#pragma unroll
        for (int s = 0; s < 2; s++) {
            const uint32_t Asl = Ab + s * SSLICE;
            const uint32_t Bsl = Bb + s * SSLICE;
            uint32_t a[16], b[8];
#pragma unroll
            for (int mt = 0; mt < 4; mt++) ldmx4(a + mt * 4, Asl + aoff[mt]);
#pragma unroll
            for (int p = 0; p < 2; p++)  ldmx4(b + p * 4, Bsl + boff[p]);
#pragma unroll
            for (int mt = 0; mt < 4; mt++)
#pragma unroll
            for (int nt = 0; nt < 4; nt++)
                mma_bf16(&cc[(mt*4+nt)*4], &a[mt*4], &b[nt*2]);
            uint32_t bs[8];
#pragma unroll
            for (int j = 0; j < 8; j++) bs[j] = hswap(b[j]);
#pragma unroll
            for (int mt = 0; mt < 4; mt++)
#pragma unroll
            for (int nt = 0; nt < 4; nt++)
                mma_bf16(&cc[(mt*4+nt)*4], &a[mt*4], &bs[nt*2]);
        }
        __syncthreads();
        if (i + 3 < 64) ISSUE(i + 3, stg);
        stg = (stg == 2) ? 0 : stg + 1;
    }

    const int ldc = (MODE == 0) ? NLIN : H_;
#pragma unroll
    for (int mt = 0; mt < 4; mt++)
#pragma unroll
    for (int nt = 0; nt < 4; nt++) {
        const int r = row0 + wm + mt * 16 + (lane >> 2);
        const int c = col0 + wn + nt * 8 + (lane & 3) * 2;
        float* p = &cc[(mt*4+nt)*4];
        if (MODE == 0) {
            *(float2*)&C[(size_t)r * ldc + c]     = make_float2(p[0], p[1]);
            *(float2*)&C[(size_t)(r+8) * ldc + c] = make_float2(p[2], p[3]);
        } else {
            const size_t o0 = (size_t)r * ldc + c, o1 = (size_t)(r+8) * ldc + c;
            float2 x0 = *(const float2*)&xres[o0];
            float2 x1 = *(const float2*)&xres[o1];
            float2 bv = *(const float2*)&bias[c];
            *(float2*)&C[o0] = make_float2(p[0] + bv.x + x0.x, p[1] + bv.y + x0.y);
            *(float2*)&C[o1] = make_float2(p[2] + bv.x + x1.x, p[3] + bv.y + x1.y);
        }
    }
#undef ISSUE
}

// ---------------- prep: RoPE + phi, beta, mix, v transpose ----------------
__global__ __launch_bounds__(512) void prep_kernel(
    const float* __restrict__ lin, const float* __restrict__ bbeta,
    const float* __restrict__ bmix,
    float* __restrict__ phiq, float* __restrict__ phik, float* __restrict__ vt,
    float* __restrict__ beta, float* __restrict__ mixo)
{
    const int bt = blockIdx.x;
    const int b  = bt >> 10;
    const int t  = bt & 1023;
    const int tid = threadIdx.x;
    const int h  = tid >> 4;
    const int i  = tid & 15;

    float inv = expf(-(float)i * (0.0625f * 9.210340371976184f));
    float ang = (float)t * inv;
    float s = sinf(ang), c = cosf(ang);

    const size_t rb = (size_t)bt * NLIN;
    size_t src = rb + (size_t)h * 32;
    float q1 = lin[src + i],        q2 = lin[src + 16 + i];
    float k1 = lin[src + 1024 + i], k2 = lin[src + 1024 + 16 + i];
    float rq1 = q1*c - q2*s, rq2 = q1*s + q2*c;
    float rk1 = k1*c - k2*s, rk2 = k1*s + k2*c;

    size_t dst = (((size_t)b * NH_ + h) * T_ + t) * D_;
    phiq[dst + i]      = (rq1 > 0.f) ? rq1 + 1.f : expf(rq1);
    phiq[dst + 16 + i] = (rq2 > 0.f) ? rq2 + 1.f : expf(rq2);
    phik[dst + i]      = (rk1 > 0.f) ? rk1 + 1.f : expf(rk1);
    phik[dst + 16 + i] = (rk2 > 0.f) ? rk2 + 1.f : expf(rk2);

    {
        int e  = tid * 2;
        int hh = e >> 5, dd = e & 31;
        float2 vv = *(const float2*)(lin + rb + 2048 + e);
        size_t vd = (((size_t)b * NH_ + hh) * T_ + t) * D_ + dd;
        *(float2*)(vt + vd) = vv;
    }

    if (tid < 64) {
        float xv = lin[rb + 3072 + tid] + bbeta[tid];
        float sg = 1.f / (1.f + expf(-xv));
        sg = fminf(fmaxf(sg, 0.85f), 0.9995f);
        int hh = tid >> 1, mm = tid & 1;
        beta[(((size_t)b * NH_ + hh) * M_ + mm) * T_ + t] = sg;
    }
    if (tid < 32) {
        int hh = tid;
        float a0 = lin[rb + 3136 + hh*2]     + bmix[hh*2];
        float a1 = lin[rb + 3136 + hh*2 + 1] + bmix[hh*2 + 1];
        float mx = fmaxf(a0, a1);
        float e0 = expf(a0 - mx), e1 = expf(a1 - mx);
        float rinv = 1.f / (e0 + e1);
        size_t base = (((size_t)b * NH_ + hh) * M_) * T_ + t;
        mixo[base]      = e0 * rinv;
        mixo[base + T_] = e1 * rinv;
    }
}

// ---------------- fused state pipeline: cumprod + chunk sums + carry ----------------
// One block per bhm. S (32x32) lives in registers (4 floats/thread).
// Per chunk: scan beta -> P/Pinv; load k,v tiles; write Scar/Kcar (entering state);
// U = K~^T V accumulated on the fly; S = PL*(S+U).
__global__ __launch_bounds__(256) void state_kernel(
    const float* __restrict__ phik, const float* __restrict__ vt,
    const float* __restrict__ beta,
    float* __restrict__ P, float* __restrict__ Scar, float* __restrict__ Kcar)
{
    const int bhm = blockIdx.x;           // 0..255
    const int bh  = bhm >> 1;
    const int tid = threadIdx.x;
    const int e   = tid >> 3;             // 0..31 (v column)
    const int x4  = (tid & 7) * 4;        // 0..28 (d group)

    __shared__ float kt[32][36];
    __shared__ float vv[32][36];
    __shared__ float Ps[32];
    __shared__ float Pinv[32];

    float S0 = 0.f, S1 = 0.f, S2 = 0.f, S3 = 0.f;
    float Kv = 0.f;                       // valid for tid<32 (d=tid)

    for (int c = 0; c < NC_; c++) {
        const int t0 = c * 32;
        // phase 1: beta scan (warp 0) + raw k/v tile loads
        if (tid < 32) {
            float v = beta[(size_t)bhm * T_ + t0 + tid];
#pragma unroll
            for (int o = 1; o < 32; o <<= 1) {
                float u = __shfl_up_sync(0xffffffffu, v, o);
                if (tid >= o) v *= u;
            }
            Ps[tid] = v;
            Pinv[tid] = 1.f / v;
            P[(size_t)bhm * T_ + t0 + tid] = v;
        }
        {
            const int tl = tid >> 3;
            size_t base = ((size_t)bh * T_ + t0 + tl) * 32 + x4;
            float4 kq = *(const float4*)(phik + base);
            kt[tl][x4+0] = kq.x; kt[tl][x4+1] = kq.y;
            kt[tl][x4+2] = kq.z; kt[tl][x4+3] = kq.w;
            float4 vz = *(const float4*)(vt + base);
            vv[tl][x4+0] = vz.x; vv[tl][x4+1] = vz.y;
            vv[tl][x4+2] = vz.z; vv[tl][x4+3] = vz.w;
        }
        __syncthreads();

        // write entering state
        *(float4*)(Scar + ((size_t)bhm * NC_ + c) * 1024 + e * 32 + x4)
            = make_float4(S0, S1, S2, S3);
        if (tid < 32) Kcar[((size_t)bhm * NC_ + c) * 32 + tid] = Kv;

        // U accumulate: u_q = sum_t (k[t][x4+q]*Pinv[t]) * v[t][e]
        const float PL = Ps[31];
        float u0 = 0.f, u1 = 0.f, u2 = 0.f, u3 = 0.f;
#pragma unroll
        for (int t = 0; t < 32; t++) {
            float ve = vv[t][e] * Pinv[t];
            u0 = fmaf(kt[t][x4+0], ve, u0);
            u1 = fmaf(kt[t][x4+1], ve, u1);
            u2 = fmaf(kt[t][x4+2], ve, u2);
            u3 = fmaf(kt[t][x4+3], ve, u3);
        }
        S0 = PL * (S0 + u0); S1 = PL * (S1 + u1);
        S2 = PL * (S2 + u2); S3 = PL * (S3 + u3);
        if (tid < 32) {
            float s = 0.f;
#pragma unroll
            for (int t = 0; t < 32; t++) s = fmaf(kt[t][tid], Pinv[t], s);
            Kv = PL * (Kv + s);
        }
        __syncthreads();
    }
}

// ---------------- per-chunk output (writes packed bf16 y) ----------------
__global__ __launch_bounds__(256) void chunk_out_kernel(
    const float* __restrict__ phiq, const float* __restrict__ phik,
    const float* __restrict__ vt,   const float* __restrict__ P,
    const float* __restrict__ mix,  const float* __restrict__ Scar,
    const float* __restrict__ Kcar, uint32_t* __restrict__ ypk)
{
    const int blk = blockIdx.x;
    const int bh = blk >> 5, c = blk & 31;
    const int t0 = c * 32;

    __shared__ float qt[32][33];
    __shared__ float kt[32][33];
    __shared__ float vv[32][33];
    __shared__ float ST[32][33];
    __shared__ float A [32][33];
    __shared__ float den[32];
    __shared__ float K0[32];

    const int tid = threadIdx.x;
    const int tl = tid >> 3;
    const int x4 = (tid & 7) * 4;
    const int lane = tid & 31, w = tid >> 5;

    size_t vbase = ((size_t)bh * T_ + t0 + tl) * 32 + x4;
    {
        float4 vz = *(const float4*)(vt + vbase);
        vv[tl][x4+0] = vz.x; vv[tl][x4+1] = vz.y; vv[tl][x4+2] = vz.z; vv[tl][x4+3] = vz.w;
    }

    float yac[4] = {0.f, 0.f, 0.f, 0.f};

    for (int m = 0; m < 2; m++) {
        const int bhm = bh * 2 + m;
        float Pt  = P[(size_t)bhm * T_ + t0 + tl];
        float inv = 1.f / Pt;
        float4 qv = *(const float4*)(phiq + vbase);
        float4 kv = *(const float4*)(phik + vbase);
        qt[tl][x4+0] = qv.x * Pt;  qt[tl][x4+1] = qv.y * Pt;
        qt[tl][x4+2] = qv.z * Pt;  qt[tl][x4+3] = qv.w * Pt;
        kt[tl][x4+0] = kv.x * inv; kt[tl][x4+1] = kv.y * inv;
        kt[tl][x4+2] = kv.z * inv; kt[tl][x4+3] = kv.w * inv;

        size_t tb = (size_t)bhm * NC_ + c;
        float4 sv = ((const float4*)(Scar + tb * 1024))[tid];
        ST[tl][x4+0] = sv.x; ST[tl][x4+1] = sv.y; ST[tl][x4+2] = sv.z; ST[tl][x4+3] = sv.w;
        if (tid < 32) K0[tid] = Kcar[tb * 32 + tid];
        __syncthreads();

        float a[4] = {0.f, 0.f, 0.f, 0.f};
#pragma unroll
        for (int d = 0; d < 32; d++) {
            float qd = qt[tl][d];
            a[0] = fmaf(qd, kt[x4+0][d], a[0]);
            a[1] = fmaf(qd, kt[x4+1][d], a[1]);
            a[2] = fmaf(qd, kt[x4+2][d], a[2]);
            a[3] = fmaf(qd, kt[x4+3][d], a[3]);
        }
#pragma unroll
        for (int q = 0; q < 4; q++)
            A[tl][x4+q] = (x4 + q <= tl) ? a[q] : 0.f;
        __syncthreads();

#pragma unroll
        for (int r = 0; r < 4; r++) {
            int t = w * 4 + r;
            float v = A[t][lane] + qt[t][lane] * K0[lane];
#pragma unroll
            for (int o = 16; o > 0; o >>= 1)
                v += __shfl_xor_sync(0xffffffffu, v, o);
            if (lane == 0) den[t] = v + 1e-6f;
        }
        __syncthreads();

        float mixv = mix[(size_t)bhm * T_ + t0 + tl];
        float f = mixv / den[tl];
        float n[4] = {0.f, 0.f, 0.f, 0.f};
#pragma unroll
        for (int j = 0; j < 32; j++) {
            float aj = A[tl][j];
            n[0] = fmaf(aj, vv[j][x4+0], n[0]);
            n[1] = fmaf(aj, vv[j][x4+1], n[1]);
            n[2] = fmaf(aj, vv[j][x4+2], n[2]);
            n[3] = fmaf(aj, vv[j][x4+3], n[3]);
        }
#pragma unroll
        for (int d = 0; d < 32; d++) {
            float qd = qt[tl][d];
            n[0] = fmaf(qd, ST[x4+0][d], n[0]);
            n[1] = fmaf(qd, ST[x4+1][d], n[1]);
            n[2] = fmaf(qd, ST[x4+2][d], n[2]);
            n[3] = fmaf(qd, ST[x4+3][d], n[3]);
        }
#pragma unroll
        for (int q = 0; q < 4; q++) yac[q] = fmaf(f, n[q], yac[q]);
        __syncthreads();
    }

    const int b = bh >> 5, h = bh & 31;
    uint4 pk;
    pk.x = packbf(yac[0]); pk.y = packbf(yac[1]);
    pk.z = packbf(yac[2]); pk.w = packbf(yac[3]);
    *(uint4*)(ypk + ((size_t)(b * T_ + t0 + tl)) * H_ + h * 32 + x4) = pk;
}

// ---------------- LayerNorm ----------------
__global__ __launch_bounds__(256) void ln_kernel(
    const float* __restrict__ z, const float* __restrict__ gamma,
    const float* __restrict__ bta, float* __restrict__ out)
{
    const int row = blockIdx.x;
    const float* zr = z + (size_t)row * H_;
    float s = 0.f, ss = 0.f;
    for (int i = threadIdx.x; i < H_; i += 256) {
        float v = zr[i]; s += v; ss = fmaf(v, v, ss);
    }
    __shared__ float sh[64];
#pragma unroll
    for (int o = 16; o > 0; o >>= 1) {
        s  += __shfl_xor_sync(0xffffffffu, s, o);
        ss += __shfl_xor_sync(0xffffffffu, ss, o);
    }
    int wid = threadIdx.x >> 5, lane = threadIdx.x & 31;
    if (lane == 0) { sh[wid] = s; sh[32 + wid] = ss; }
    __syncthreads();
    if (threadIdx.x < 32) {
        float a = (threadIdx.x < 8) ? sh[threadIdx.x] : 0.f;
        float c = (threadIdx.x < 8) ? sh[32 + threadIdx.x] : 0.f;
#pragma unroll
        for (int o = 4; o > 0; o >>= 1) {
            a += __shfl_xor_sync(0xffffffffu, a, o);
            c += __shfl_xor_sync(0xffffffffu, c, o);
        }
        if (threadIdx.x == 0) { sh[0] = a; sh[1] = c; }
    }
    __syncthreads();
    float mu  = sh[0] * (1.f / H_);
    float var = sh[1] * (1.f / H_) - mu * mu;
    float rstd = rsqrtf(var + 1e-5f);
    for (int i = threadIdx.x; i < H_; i += 256)
        out[(size_t)row * H_ + i] = (zr[i] - mu) * rstd * gamma[i] + bta[i];
}

// ---------------- launch ----------------
extern "C" void kernel_launch(void* const* d_in, const int* in_sizes, int n_in,
                              void* d_out, int out_size)
{
    const float* x     = (const float*)d_in[0];
    const float* Wq    = (const float*)d_in[1];
    const float* Wk    = (const float*)d_in[2];
    const float* Wv    = (const float*)d_in[3];
    const float* Wbeta = (const float*)d_in[4];
    const float* bbeta = (const float*)d_in[5];
    const float* Wmix  = (const float*)d_in[6];
    const float* bmix  = (const float*)d_in[7];
    const float* Wout  = (const float*)d_in[8];
    const float* bout  = (const float*)d_in[9];
    const float* ln_g  = (const float*)d_in[10];
    const float* ln_b  = (const float*)d_in[11];
    float* out = (float*)d_out;

    uint32_t *xpk,*wpk,*ypk;
    float *lin,*phiq,*phik,*vt,*beta,*mix,*P,*Scar,*Kcar,*z;
    cudaGetSymbolAddress((void**)&xpk,  g_xpk);
    cudaGetSymbolAddress((void**)&wpk,  g_wpk);
    cudaGetSymbolAddress((void**)&ypk,  g_ypk);
    cudaGetSymbolAddress((void**)&lin,  g_lin);
    cudaGetSymbolAddress((void**)&phiq, g_phiq);
    cudaGetSymbolAddress((void**)&phik, g_phik);
    cudaGetSymbolAddress((void**)&vt,   g_vt);
    cudaGetSymbolAddress((void**)&beta, g_beta);
    cudaGetSymbolAddress((void**)&mix,  g_mix);
    cudaGetSymbolAddress((void**)&P,    g_P);
    cudaGetSymbolAddress((void**)&Scar, g_Scar);
    cudaGetSymbolAddress((void**)&Kcar, g_Kcar);
    cudaGetSymbolAddress((void**)&z,    g_z);

    cudaFuncSetAttribute(gemm_bf<0>, cudaFuncAttributeMaxDynamicSharedMemorySize, GSMEM_BYTES);
    cudaFuncSetAttribute(gemm_bf<2>, cudaFuncAttributeMaxDynamicSharedMemorySize, GSMEM_BYTES);

    // ---- pack operands ----
    split_kernel<<<4096, 256>>>(x, xpk, (B_*T_*K_)/4);
    split_w_kernel<<<WROWS, 256>>>(Wq, Wk, Wv, Wbeta, Wmix, Wout, wpk);

    // ---- fused q/k/v/beta/mix projection ----
    gemm_bf<0><<<dim3(NLIN/128, 32), 256, GSMEM_BYTES>>>(xpk, wpk, lin, nullptr, nullptr);

    prep_kernel<<<B_*T_, 512>>>(lin, bbeta, bmix, phiq, phik, vt, beta, mix);

    // ---- fused state pipeline + per-chunk output ----
    state_kernel<<<BHM_, 256>>>(phik, vt, beta, P, Scar, Kcar);
    chunk_out_kernel<<<B_*NH_*NC_, 256>>>(phiq, phik, vt, P, mix, Scar, Kcar, ypk);

    // ---- output projection ----
    gemm_bf<2><<<dim3(8, 32), 256, GSMEM_BYTES>>>(ypk, wpk + (size_t)3200*K_, z, bout, x);

    ln_kernel<<<B_*T_, 256>>>(z, ln_g, ln_b, out);
}